// round 13
// baseline (speedup 1.0000x reference)
#include <cuda_runtime.h>
#include <math.h>

#define B_  2
#define E_  1024
#define DM_ 512
#define H_  8
#define DK_ 64
#define DV_ 64
#define MAXN_ 5
#define NEGV (-1e9f)

__device__ __forceinline__ float tf32q(float x) {
    unsigned u;
    asm("cvt.rna.tf32.f32 %0, %1;" : "=r"(u) : "f"(x));
    return __uint_as_float(u);
}
__device__ __forceinline__ float4 tf32q4(float4 v) {
    v.x = tf32q(v.x); v.y = tf32q(v.y); v.z = tf32q(v.z); v.w = tf32q(v.w);
    return v;
}

#define MMA8(d, a, b)                                                        \
    asm volatile(                                                            \
        "mma.sync.aligned.m16n8k8.row.col.f32.tf32.tf32.f32 "                \
        "{%0,%1,%2,%3}, {%4,%5,%6,%7}, {%8,%9}, {%0,%1,%2,%3};\n"            \
        : "+f"((d)[0]), "+f"((d)[1]), "+f"((d)[2]), "+f"((d)[3])             \
        : "r"((a)[0]), "r"((a)[1]), "r"((a)[2]), "r"((a)[3]),                \
          "r"((b)[0]), "r"((b)[1]));

#define CP_ASYNC16(su, gp)                                                   \
    asm volatile("cp.async.cg.shared.global [%0], [%1], 16;\n"               \
                 :: "r"(su), "l"(gp) : "memory")
#define CP_COMMIT  asm volatile("cp.async.commit_group;\n" ::: "memory")
#define CP_WAIT0   asm volatile("cp.async.wait_group 0;\n" ::: "memory")

// ---------------- scratch ---------------------------------------------------
__device__ float g_s  [B_*E_*DM_];       // exact (LN stats + FC residual)
__device__ float g_sq [B_*E_*DM_];       // tf32-rounded (K/V GEMM input)
__device__ float g_qn [B_*E_*DM_];       // LN output, tf32-rounded
__device__ float g_q  [B_*H_*E_*DK_];    // tf32-rounded
__device__ float g_k  [B_*H_*E_*DK_];    // tf32-rounded
__device__ float g_v  [B_*H_*E_*DV_];    // tf32-rounded
__device__ float g_o  [B_*E_*H_*DV_];    // tf32-rounded
__device__ float g_wq  [3*DM_*(H_*DK_)]; // quantized w_q|w_k|w_v
__device__ float g_wfcq[DM_*DM_];        // quantized w_fc
__device__ float g_pcs2[B_*H_*16*E_];
__device__ unsigned char g_d8[B_*E_*E_];

// ---------------- 1. transpose x[b,d,e] -> s[b,e,d] (+tf32 copy) ------------
__global__ void k_transpose(const float* __restrict__ x) {
    __shared__ float tile[32][33];
    int b = blockIdx.z;
    int e0 = blockIdx.x * 32;
    int d0 = blockIdx.y * 32;
    int tx = threadIdx.x, ty = threadIdx.y;
#pragma unroll
    for (int r = 0; r < 4; r++) {
        int d = d0 + ty + r * 8;
        tile[ty + r * 8][tx] = x[(size_t)b * DM_ * E_ + (size_t)d * E_ + e0 + tx];
    }
    __syncthreads();
#pragma unroll
    for (int r = 0; r < 4; r++) {
        int e = e0 + ty + r * 8;
        float v = tile[tx][ty + r * 8];
        size_t idx = (size_t)b * E_ * DM_ + (size_t)e * DM_ + d0 + tx;
        g_s[idx]  = v;
        g_sq[idx] = tf32q(v);
    }
}

// ---------------- 2. LayerNorm (tf32-rounded output) -------------------------
__global__ void k_layernorm(const float* __restrict__ ln_g, const float* __restrict__ ln_b) {
    int row = blockIdx.x;
    const float* src = g_s + (size_t)row * DM_;
    int tid = threadIdx.x;
    float2 v = ((const float2*)src)[tid];
    float s1 = v.x + v.y;
    float s2 = v.x * v.x + v.y * v.y;
#pragma unroll
    for (int o = 16; o; o >>= 1) {
        s1 += __shfl_xor_sync(0xffffffff, s1, o);
        s2 += __shfl_xor_sync(0xffffffff, s2, o);
    }
    __shared__ float sh[16];
    __shared__ float s_mu, s_rstd;
    int w = tid >> 5, l = tid & 31;
    if (l == 0) { sh[w] = s1; sh[8 + w] = s2; }
    __syncthreads();
    if (tid == 0) {
        float a = 0.f, c = 0.f;
#pragma unroll
        for (int i = 0; i < 8; i++) { a += sh[i]; c += sh[8 + i]; }
        float mu  = a / (float)DM_;
        float var = c / (float)DM_ - mu * mu;
        s_mu = mu;
        s_rstd = 1.f / sqrtf(var + 1e-6f);
    }
    __syncthreads();
    float mu = s_mu, rstd = s_rstd;
    float2 gg = ((const float2*)ln_g)[tid];
    float2 bb = ((const float2*)ln_b)[tid];
    float2 o;
    o.x = tf32q((v.x - mu) * rstd * gg.x + bb.x);
    o.y = tf32q((v.y - mu) * rstd * gg.y + bb.y);
    ((float2*)(g_qn + (size_t)row * DM_))[tid] = o;
}

// ---------------- 3. pack dist -> int8 + quantize weights --------------------
__global__ void k_pack_prep(const int* __restrict__ dist,
                            const float* __restrict__ w_q,
                            const float* __restrict__ w_k,
                            const float* __restrict__ w_v,
                            const float* __restrict__ w_fc) {
    int bid = blockIdx.x;
    if (bid < 2048) {
        int idx = bid * 256 + threadIdx.x;
        int4 v = ((const int4*)dist)[idx];
        uchar4 o;
        o.x = (unsigned char)(v.x > 7 ? 7 : v.x);
        o.y = (unsigned char)(v.y > 7 ? 7 : v.y);
        o.z = (unsigned char)(v.z > 7 ? 7 : v.z);
        o.w = (unsigned char)(v.w > 7 ? 7 : v.w);
        ((uchar4*)g_d8)[idx] = o;
    } else {
        int idx = (bid - 2048) * 256 + threadIdx.x;
        int matid = idx >> 16;
        int off = idx & 65535;
        const float* src = (matid == 0) ? w_q : (matid == 1) ? w_k
                          : (matid == 2) ? w_v : w_fc;
        float4 v = tf32q4(((const float4*)src)[off]);
        float* dst = (matid < 3) ? (g_wq + (size_t)matid * DM_ * 512)
                                 : g_wfcq;
        ((float4*)dst)[off] = v;
    }
}

// ---------------- 4. QKV GEMM: 128x128 tiles, cp.async double-buffered -------
// grid (E/128, 4, 3*B): z = mat*B + b. Warp grid 2(warpM,64rows) x 4(warpN,32cols).
// smem: A0 @0 (128*36=4608), A1 @4608, W0 @9216 (32*136=4352), W1 @13568; 17920 f
#define QKV_SM 17920
__global__ __launch_bounds__(256) void k_qkv_mma() {
    extern __shared__ float qsm[];
    float* Ab[2] = { qsm, qsm + 4608 };
    float* Wb[2] = { qsm + 9216, qsm + 13568 };
    unsigned a_u[2] = { (unsigned)__cvta_generic_to_shared(Ab[0]),
                        (unsigned)__cvta_generic_to_shared(Ab[1]) };
    unsigned w_u[2] = { (unsigned)__cvta_generic_to_shared(Wb[0]),
                        (unsigned)__cvta_generic_to_shared(Wb[1]) };

    int z = blockIdx.z;
    int mat = z >> 1, b = z & 1;
    int m0 = blockIdx.x * 128;
    int n0 = blockIdx.y * 128;
    const float* A = (mat == 0) ? g_qn : g_sq;
    const float* W = g_wq + (size_t)mat * DM_ * 512;
    float* out = (mat == 0) ? g_q : (mat == 1 ? g_k : g_v);
    float scale = (mat == 0) ? 0.125f : 1.0f;

    int tid = threadIdx.x;
    int wid = tid >> 5, lane = tid & 31;
    int g = lane >> 2, t = lane & 3;
    int warpM = wid & 1, warpN = wid >> 1;

    float acc[4][4][4] = {};
    size_t arow_base = ((size_t)b * E_ + m0);

    // preload chunk 0
    {
#pragma unroll
        for (int i = 0; i < 4; i++) {
            int f = tid + i * 256;
            int row = f >> 3, c4 = (f & 7) * 4;
            CP_ASYNC16(a_u[0] + (unsigned)(row * 36 + c4) * 4,
                       A + (arow_base + row) * DM_ + c4);
        }
#pragma unroll
        for (int i = 0; i < 4; i++) {
            int f = tid + i * 256;
            int row = f >> 5, c4 = (f & 31) * 4;
            CP_ASYNC16(w_u[0] + (unsigned)(row * 136 + c4) * 4,
                       W + (size_t)row * 512 + n0 + c4);
        }
        CP_COMMIT;
    }
    int cur = 0;
    for (int k0 = 0; k0 < DM_; k0 += 32) {
        CP_WAIT0;
        __syncthreads();
        if (k0 + 32 < DM_) {
            unsigned au = a_u[cur ^ 1], wu = w_u[cur ^ 1];
#pragma unroll
            for (int i = 0; i < 4; i++) {
                int f = tid + i * 256;
                int row = f >> 3, c4 = (f & 7) * 4;
                CP_ASYNC16(au + (unsigned)(row * 36 + c4) * 4,
                           A + (arow_base + row) * DM_ + k0 + 32 + c4);
            }
#pragma unroll
            for (int i = 0; i < 4; i++) {
                int f = tid + i * 256;
                int row = f >> 5, c4 = (f & 31) * 4;
                CP_ASYNC16(wu + (unsigned)(row * 136 + c4) * 4,
                           W + (size_t)(k0 + 32 + row) * 512 + n0 + c4);
            }
            CP_COMMIT;
        }
        const unsigned* Asu = (const unsigned*)Ab[cur];
        const unsigned* Wsu = (const unsigned*)Wb[cur];
#pragma unroll
        for (int kk = 0; kk < 4; kk++) {
            int k = kk * 8;
            unsigned af[4][4], bf[4][2];
#pragma unroll
            for (int mb = 0; mb < 4; mb++) {
                int rb = warpM * 64 + mb * 16;
                af[mb][0] = Asu[(rb + g) * 36 + k + t];
                af[mb][1] = Asu[(rb + g + 8) * 36 + k + t];
                af[mb][2] = Asu[(rb + g) * 36 + k + t + 4];
                af[mb][3] = Asu[(rb + g + 8) * 36 + k + t + 4];
            }
#pragma unroll
            for (int nb = 0; nb < 4; nb++) {
                int cb = warpN * 32 + nb * 8 + g;
                bf[nb][0] = Wsu[(k + t) * 136 + cb];
                bf[nb][1] = Wsu[(k + t + 4) * 136 + cb];
            }
#pragma unroll
            for (int mb = 0; mb < 4; mb++)
#pragma unroll
                for (int nb = 0; nb < 4; nb++) MMA8(acc[mb][nb], af[mb], bf[nb])
        }
        cur ^= 1;
    }
    // store: col c -> head (n0+c)>>6, dk = c&63
#pragma unroll
    for (int mb = 0; mb < 4; mb++) {
        size_t r0 = (size_t)(m0 + warpM * 64 + mb * 16 + g);
#pragma unroll
        for (int nb = 0; nb < 4; nb++) {
            int c = warpN * 32 + nb * 8 + 2 * t;
            int h = (n0 + c) >> 6;
            int dk = c & 63;
            size_t obase = (((size_t)b * H_ + h) * E_) * 64 + dk;
            *(float2*)(out + obase + (r0) * 64) =
                make_float2(tf32q(acc[mb][nb][0] * scale), tf32q(acc[mb][nb][1] * scale));
            *(float2*)(out + obase + (r0 + 8) * 64) =
                make_float2(tf32q(acc[mb][nb][2] * scale), tf32q(acc[mb][nb][3] * scale));
        }
    }
}

// ---------------- 5. flash (no-max softmax): QK+exp+O, double-buffered --------
// grid (16, B*H): block owns 64 i-rows. warps: 4(warpM,16rows) x 2(warpN,32cols).
#define SM_QS    0
#define SM_KP0   4352
#define SM_KP1   8704
#define SM_VS0   13056
#define SM_VS1   17664
#define SM_RPR   22272
#define SM_QRS   22656
#define SM_ROWL  23040
#define SM_LINV  23168
#define SM_TOTAL 23232   // floats

__global__ __launch_bounds__(256) void k_flash(
    const float* __restrict__ base_rpr, float* __restrict__ attn)
{
    extern __shared__ float sm[];
    float* Qs     = sm + SM_QS;
    float* rpr_s  = sm + SM_RPR;
    float* qrs    = sm + SM_QRS;
    float* rowl   = sm + SM_ROWL;
    float* linv_s = sm + SM_LINV;
    float* KPb[2] = { sm + SM_KP0, sm + SM_KP1 };
    float* Vsb[2] = { sm + SM_VS0, sm + SM_VS1 };
    unsigned kp_u[2] = { (unsigned)__cvta_generic_to_shared(KPb[0]),
                         (unsigned)__cvta_generic_to_shared(KPb[1]) };
    unsigned vs_u[2] = { (unsigned)__cvta_generic_to_shared(Vsb[0]),
                         (unsigned)__cvta_generic_to_shared(Vsb[1]) };

    int iblk = blockIdx.x, i0 = iblk * 64;
    int z = blockIdx.y, b = z >> 3;
    int tid = threadIdx.x, wid = tid >> 5, lane = tid & 31;
    int g = lane >> 2, t = lane & 3;
    int warpM = wid & 3, warpN = wid >> 2;

    const unsigned* Qsu = (const unsigned*)Qs;

    size_t qbase = ((size_t)z * E_ + i0) * 64;
    size_t kvbase = (size_t)z * E_ * 64;
    const unsigned char* dbase = g_d8 + (size_t)b * E_ * E_;
    float* abase = attn + (size_t)z * E_ * E_;

#pragma unroll
    for (int i = 0; i < 4; i++) {
        int f = tid + i * 256;
        int row = f >> 4, c4 = (f & 15) * 4;
        *(float4*)&Qs[row * 68 + c4] =
            *(const float4*)(g_q + qbase + (size_t)row * 64 + c4);
    }
    for (int tt = tid; tt < 384; tt += 256) rpr_s[tt] = tf32q(base_rpr[tt]);

    {
        const float* kg = g_k + kvbase;
        const float* vg = g_v + kvbase;
#pragma unroll
        for (int i = 0; i < 4; i++) {
            int f = tid + i * 256;
            int row = f >> 4, c4 = (f & 15) * 4;
            CP_ASYNC16(kp_u[0] + (unsigned)(row * 68 + c4) * 4, kg + row * 64 + c4);
            CP_ASYNC16(vs_u[0] + (unsigned)(row * 72 + c4) * 4, vg + row * 64 + c4);
        }
        CP_COMMIT;
    }
    __syncthreads();
    for (int tt = tid; tt < 384; tt += 256) {
        int row = tt / 6, c = tt % 6;
        float s = 0.f;
#pragma unroll 16
        for (int d = 0; d < 64; d++) s += Qs[row * 68 + d] * rpr_s[c * 64 + d];
        qrs[tt] = s;
    }

    int il0 = warpM * 16 + g, il1 = il0 + 8;
    int gi0 = i0 + il0, gi1 = i0 + il1;

    float l[2] = {0.f, 0.f};
    float oacc[4][4] = {};
    int cur = 0;

    for (int jt = 0; jt < 16; jt++) {
        int j0 = jt * 64;
        CP_WAIT0;
        __syncthreads();                       // buf[cur] ready, prev PV done
        if (jt < 15) {
            const float* kg = g_k + kvbase + (size_t)(j0 + 64) * 64;
            const float* vg = g_v + kvbase + (size_t)(j0 + 64) * 64;
            unsigned kb = kp_u[cur ^ 1], vb = vs_u[cur ^ 1];
#pragma unroll
            for (int i = 0; i < 4; i++) {
                int f = tid + i * 256;
                int row = f >> 4, c4 = (f & 15) * 4;
                CP_ASYNC16(kb + (unsigned)(row * 68 + c4) * 4, kg + row * 64 + c4);
                CP_ASYNC16(vb + (unsigned)(row * 72 + c4) * 4, vg + row * 64 + c4);
            }
            CP_COMMIT;
        }
        const unsigned* KPu = (const unsigned*)KPb[cur];
        const unsigned* Vsu = (const unsigned*)Vsb[cur];
        // QK mma
        float acc[4][4] = {};
#pragma unroll
        for (int kk = 0; kk < 8; kk++) {
            int k = kk * 8;
            unsigned af[4];
            int rb = warpM * 16;
            af[0] = Qsu[(rb + g) * 68 + k + t];
            af[1] = Qsu[(rb + g + 8) * 68 + k + t];
            af[2] = Qsu[(rb + g) * 68 + k + t + 4];
            af[3] = Qsu[(rb + g + 8) * 68 + k + t + 4];
#pragma unroll
            for (int nb = 0; nb < 4; nb++) {
                unsigned bf[2];
                int cb = warpN * 32 + nb * 8 + g;
                bf[0] = KPu[cb * 68 + k + t];
                bf[1] = KPu[cb * 68 + k + t + 4];
                MMA8(acc[nb], af, bf)
            }
        }
        // p = exp(x) (masked -> 0), write unnormalized, accumulate l
        float p[4][4];
#pragma unroll
        for (int nb = 0; nb < 4; nb++) {
            int j = j0 + warpN * 32 + nb * 8 + 2 * t;
            uchar2 d0 = *(const uchar2*)(dbase + (size_t)gi0 * E_ + j);
            uchar2 d1 = *(const uchar2*)(dbase + (size_t)gi1 * E_ + j);
            p[nb][0] = (d0.x <= MAXN_) ? __expf(acc[nb][0] + qrs[il0 * 6 + d0.x]) : 0.f;
            p[nb][1] = (d0.y <= MAXN_) ? __expf(acc[nb][1] + qrs[il0 * 6 + d0.y]) : 0.f;
            p[nb][2] = (d1.x <= MAXN_) ? __expf(acc[nb][2] + qrs[il1 * 6 + d1.x]) : 0.f;
            p[nb][3] = (d1.y <= MAXN_) ? __expf(acc[nb][3] + qrs[il1 * 6 + d1.y]) : 0.f;
            l[0] += p[nb][0] + p[nb][1];
            l[1] += p[nb][2] + p[nb][3];
            *(float2*)(abase + (size_t)gi0 * E_ + j) = make_float2(p[nb][0], p[nb][1]);
            *(float2*)(abase + (size_t)gi1 * E_ + j) = make_float2(p[nb][2], p[nb][3]);
        }
        __syncthreads();                        // all QK reads of KP[cur] done
        float* KPw = KPb[cur];
#pragma unroll
        for (int nb = 0; nb < 4; nb++) {
            int jl = warpN * 32 + nb * 8 + 2 * t;
            KPw[il0 * 68 + jl]     = tf32q(p[nb][0]);
            KPw[il0 * 68 + jl + 1] = tf32q(p[nb][1]);
            KPw[il1 * 68 + jl]     = tf32q(p[nb][2]);
            KPw[il1 * 68 + jl + 1] = tf32q(p[nb][3]);
        }
        __syncthreads();                        // P ready
        // O += P(64x64) @ V(64x64)
#pragma unroll
        for (int kk = 0; kk < 8; kk++) {
            int k = kk * 8;
            unsigned af[4];
            int rb = warpM * 16;
            af[0] = KPu[(rb + g) * 68 + k + t];
            af[1] = KPu[(rb + g + 8) * 68 + k + t];
            af[2] = KPu[(rb + g) * 68 + k + t + 4];
            af[3] = KPu[(rb + g + 8) * 68 + k + t + 4];
#pragma unroll
            for (int nb = 0; nb < 4; nb++) {
                unsigned bf[2];
                int cb = warpN * 32 + nb * 8 + g;
                bf[0] = Vsu[(k + t) * 72 + cb];
                bf[1] = Vsu[(k + t + 4) * 72 + cb];
                MMA8(oacc[nb], af, bf)
            }
        }
        cur ^= 1;
    }
    // reduce l over t lanes + 2 warpN warps
#pragma unroll
    for (int off = 1; off < 4; off <<= 1) {
        l[0] += __shfl_xor_sync(0xffffffff, l[0], off);
        l[1] += __shfl_xor_sync(0xffffffff, l[1], off);
    }
    if (t == 0) {
        rowl[il0 * 2 + warpN] = l[0];
        rowl[il1 * 2 + warpN] = l[1];
    }
    __syncthreads();
    if (tid < 64) linv_s[tid] = 1.f / (rowl[tid * 2] + rowl[tid * 2 + 1]);
    __syncthreads();
    float inv0 = linv_s[il0], inv1 = linv_s[il1];
    int h = z & 7;
#pragma unroll
    for (int nb = 0; nb < 4; nb++) {
        int dv = h * 64 + warpN * 32 + nb * 8 + 2 * t;
        *(float2*)(g_o + ((size_t)b * E_ + gi0) * 512 + dv) =
            make_float2(tf32q(oacc[nb][0] * inv0), tf32q(oacc[nb][1] * inv0));
        *(float2*)(g_o + ((size_t)b * E_ + gi1) * 512 + dv) =
            make_float2(tf32q(oacc[nb][2] * inv1), tf32q(oacc[nb][3] * inv1));
    }
    // fused fixup: rescale own rows by 1/l (L2-hot) + ape column partials
    {
        int j = tid * 4;
        float4 cs = make_float4(0.f, 0.f, 0.f, 0.f);
        float* arow = abase + (size_t)i0 * E_ + j;
#pragma unroll 4
        for (int r = 0; r < 64; r++) {
            float fac = linv_s[r];
            float4 x = *(float4*)(arow + (size_t)r * E_);
            x.x *= fac; x.y *= fac; x.z *= fac; x.w *= fac;
            *(float4*)(arow + (size_t)r * E_) = x;
            cs.x += x.x; cs.y += x.y; cs.z += x.z; cs.w += x.w;
        }
        *(float4*)(g_pcs2 + ((size_t)z * 16 + iblk) * E_ + j) = cs;
    }
}

// ---------------- 6. FC + residual (cp.async double-buffered) ----------------
#define FC_SM 13824
__global__ __launch_bounds__(256) void k_fc_mma(float* __restrict__ xout) {
    extern __shared__ float fsm[];
    float* Ab[2] = { fsm, fsm + 4608 };
    float* Wb[2] = { fsm + 9216, fsm + 11520 };
    unsigned a_u[2] = { (unsigned)__cvta_generic_to_shared(Ab[0]),
                        (unsigned)__cvta_generic_to_shared(Ab[1]) };
    unsigned w_u[2] = { (unsigned)__cvta_generic_to_shared(Wb[0]),
                        (unsigned)__cvta_generic_to_shared(Wb[1]) };
    int m0 = blockIdx.x * 128, n0 = blockIdx.y * 64;
    int b = m0 >> 10, e0 = m0 & 1023;
    int tid = threadIdx.x;
    int wid = tid >> 5, lane = tid & 31;
    int g = lane >> 2, t = lane & 3;
    int warpM = wid & 3, warpN = wid >> 2;

    float acc[2][4][4] = {};

    {
#pragma unroll
        for (int i = 0; i < 4; i++) {
            int f = tid + i * 256;
            int row = f >> 3, c4 = (f & 7) * 4;
            CP_ASYNC16(a_u[0] + (unsigned)(row * 36 + c4) * 4,
                       g_o + (size_t)(m0 + row) * 512 + c4);
        }
#pragma unroll
        for (int i = 0; i < 2; i++) {
            int f = tid + i * 256;
            int row = f >> 4, c4 = (f & 15) * 4;
            CP_ASYNC16(w_u[0] + (unsigned)(row * 72 + c4) * 4,
                       g_wfcq + (size_t)row * 512 + n0 + c4);
        }
        CP_COMMIT;
    }
    int cur = 0;
    for (int k0 = 0; k0 < 512; k0 += 32) {
        CP_WAIT0;
        __syncthreads();
        if (k0 + 32 < 512) {
            unsigned au = a_u[cur ^ 1], wu = w_u[cur ^ 1];
#pragma unroll
            for (int i = 0; i < 4; i++) {
                int f = tid + i * 256;
                int row = f >> 3, c4 = (f & 7) * 4;
                CP_ASYNC16(au + (unsigned)(row * 36 + c4) * 4,
                           g_o + (size_t)(m0 + row) * 512 + k0 + 32 + c4);
            }
#pragma unroll
            for (int i = 0; i < 2; i++) {
                int f = tid + i * 256;
                int row = f >> 4, c4 = (f & 15) * 4;
                CP_ASYNC16(wu + (unsigned)(row * 72 + c4) * 4,
                           g_wfcq + (size_t)(k0 + 32 + row) * 512 + n0 + c4);
            }
            CP_COMMIT;
        }
        const unsigned* Asu = (const unsigned*)Ab[cur];
        const unsigned* Wsu = (const unsigned*)Wb[cur];
#pragma unroll
        for (int kk = 0; kk < 4; kk++) {
            int k = kk * 8;
            unsigned af[2][4], bf[4][2];
#pragma unroll
            for (int mb = 0; mb < 2; mb++) {
                int rb = warpM * 32 + mb * 16;
                af[mb][0] = Asu[(rb + g) * 36 + k + t];
                af[mb][1] = Asu[(rb + g + 8) * 36 + k + t];
                af[mb][2] = Asu[(rb + g) * 36 + k + t + 4];
                af[mb][3] = Asu[(rb + g + 8) * 36 + k + t + 4];
            }
#pragma unroll
            for (int nb = 0; nb < 4; nb++) {
                int cb = warpN * 32 + nb * 8 + g;
                bf[nb][0] = Wsu[(k + t) * 72 + cb];
                bf[nb][1] = Wsu[(k + t + 4) * 72 + cb];
            }
#pragma unroll
            for (int mb = 0; mb < 2; mb++)
#pragma unroll
                for (int nb = 0; nb < 4; nb++) MMA8(acc[mb][nb], af[mb], bf[nb])
        }
        cur ^= 1;
    }
    __syncthreads();
#pragma unroll
    for (int mb = 0; mb < 2; mb++) {
        int el0 = warpM * 32 + mb * 16 + g;
#pragma unroll
        for (int nb = 0; nb < 4; nb++) {
            int nl = warpN * 32 + nb * 8 + 2 * t;
#pragma unroll
            for (int half = 0; half < 2; half++) {
                int el = el0 + half * 8;
                const float* res = g_s + (size_t)(m0 + el) * DM_ + n0 + nl;
                fsm[(nl + 0) * 132 + el] = acc[mb][nb][half * 2 + 0] + res[0];
                fsm[(nl + 1) * 132 + el] = acc[mb][nb][half * 2 + 1] + res[1];
            }
        }
    }
    __syncthreads();
#pragma unroll
    for (int i = 0; i < 8; i++) {
        int f = tid + i * 256;
        int row = f >> 5, c4 = (f & 31) * 4;
        float4 v = *(const float4*)&fsm[row * 132 + c4];
        *(float4*)(xout + ((size_t)b * DM_ + n0 + row) * E_ + e0 + c4) = v;
    }
}

// ---------------- 7. ape final -------------------------------------------------
__global__ void k_ape_final(float* __restrict__ ape) {
    int idx = blockIdx.x * 256 + threadIdx.x;
    int b = idx >> 10, j = idx & (E_ - 1);
    float cs = 0.f;
    const float* p = g_pcs2 + (size_t)b * 8 * 16 * E_ + j;
#pragma unroll 8
    for (int k = 0; k < 128; k++) cs += p[(size_t)k * E_];
    const unsigned char* dcol = g_d8 + (size_t)b * E_ * E_ + j;
    int cnt = 0;
#pragma unroll 8
    for (int i = 0; i < E_; i++) cnt += (dcol[(size_t)i * E_] <= MAXN_) ? 1 : 0;
    ape[idx] = cs / (float)cnt;
}

// ---------------- launch ------------------------------------------------------
extern "C" void kernel_launch(void* const* d_in, const int* in_sizes, int n_in,
                              void* d_out, int out_size) {
    const float* x        = (const float*)d_in[0];
    const int*   dist     = (const int*)  d_in[1];
    const float* base_rpr = (const float*)d_in[2];
    const float* w_q      = (const float*)d_in[3];
    const float* w_k      = (const float*)d_in[4];
    const float* w_v      = (const float*)d_in[5];
    const float* w_fc     = (const float*)d_in[6];
    const float* ln_g     = (const float*)d_in[7];
    const float* ln_b     = (const float*)d_in[8];

    float* x_out = (float*)d_out;
    float* attn  = x_out + (size_t)B_ * DM_ * E_;
    float* ape   = attn  + (size_t)B_ * H_ * E_ * E_;

    static int smem_set = 0;
    if (!smem_set) {
        cudaFuncSetAttribute(k_flash, cudaFuncAttributeMaxDynamicSharedMemorySize,
                             SM_TOTAL * 4);
        cudaFuncSetAttribute(k_qkv_mma, cudaFuncAttributeMaxDynamicSharedMemorySize,
                             QKV_SM * 4);
        cudaFuncSetAttribute(k_fc_mma, cudaFuncAttributeMaxDynamicSharedMemorySize,
                             FC_SM * 4);
        smem_set = 1;
    }

    k_transpose<<<dim3(E_ / 32, DM_ / 32, B_), dim3(32, 8)>>>(x);
    k_layernorm<<<B_ * E_, 256>>>(ln_g, ln_b);
    k_pack_prep<<<3072, 256>>>(dist, w_q, w_k, w_v, w_fc);

    k_qkv_mma<<<dim3(E_ / 128, 4, 3 * B_), 256, QKV_SM * 4>>>();

    k_flash<<<dim3(16, B_ * H_), 256, SM_TOTAL * 4>>>(base_rpr, attn);
    k_fc_mma<<<dim3(B_ * E_ / 128, DM_ / 64, 1), 256, FC_SM * 4>>>(x_out);
    k_ape_final<<<(B_ * E_) / 256, 256>>>(ape);
}

// round 14
// speedup vs baseline: 1.0625x; 1.0625x over previous
#include <cuda_runtime.h>
#include <math.h>

#define B_  2
#define E_  1024
#define DM_ 512
#define H_  8
#define DK_ 64
#define DV_ 64
#define MAXN_ 5

__device__ __forceinline__ float tf32q(float x) {
    unsigned u;
    asm("cvt.rna.tf32.f32 %0, %1;" : "=r"(u) : "f"(x));
    return __uint_as_float(u);
}
__device__ __forceinline__ float4 tf32q4(float4 v) {
    v.x = tf32q(v.x); v.y = tf32q(v.y); v.z = tf32q(v.z); v.w = tf32q(v.w);
    return v;
}

#define MMA8(d, a, b)                                                        \
    asm volatile(                                                            \
        "mma.sync.aligned.m16n8k8.row.col.f32.tf32.tf32.f32 "                \
        "{%0,%1,%2,%3}, {%4,%5,%6,%7}, {%8,%9}, {%0,%1,%2,%3};\n"            \
        : "+f"((d)[0]), "+f"((d)[1]), "+f"((d)[2]), "+f"((d)[3])             \
        : "r"((a)[0]), "r"((a)[1]), "r"((a)[2]), "r"((a)[3]),                \
          "r"((b)[0]), "r"((b)[1]));

#define CP_ASYNC16(su, gp)                                                   \
    asm volatile("cp.async.cg.shared.global [%0], [%1], 16;\n"               \
                 :: "r"(su), "l"(gp) : "memory")
#define CP_COMMIT  asm volatile("cp.async.commit_group;\n" ::: "memory")
#define CP_WAIT0   asm volatile("cp.async.wait_group 0;\n" ::: "memory")

// ---------------- scratch ---------------------------------------------------
__device__ float g_s  [B_*E_*DM_];       // exact (LN stats + FC residual)
__device__ float g_sq [B_*E_*DM_];       // tf32-rounded (K/V GEMM input)
__device__ float g_qn [B_*E_*DM_];       // LN output, tf32-rounded
__device__ float g_q  [B_*H_*E_*DK_];    // tf32-rounded
__device__ float g_k  [B_*H_*E_*DK_];    // tf32-rounded
__device__ float g_v  [B_*H_*E_*DV_];    // tf32-rounded
__device__ float g_o  [B_*E_*H_*DV_];    // tf32-rounded
__device__ float g_wq  [3*DM_*(H_*DK_)]; // quantized w_q|w_k|w_v
__device__ float g_wfcq[DM_*DM_];        // quantized w_fc
__device__ float g_pcs2[B_*H_*16*E_];
__device__ unsigned char g_d8[B_*E_*E_];

// ---------------- 1. transpose x[b,d,e] -> s[b,e,d] (+tf32 copy) ------------
__global__ void k_transpose(const float* __restrict__ x) {
    __shared__ float tile[32][33];
    int b = blockIdx.z;
    int e0 = blockIdx.x * 32;
    int d0 = blockIdx.y * 32;
    int tx = threadIdx.x, ty = threadIdx.y;
#pragma unroll
    for (int r = 0; r < 4; r++) {
        int d = d0 + ty + r * 8;
        tile[ty + r * 8][tx] = x[(size_t)b * DM_ * E_ + (size_t)d * E_ + e0 + tx];
    }
    __syncthreads();
#pragma unroll
    for (int r = 0; r < 4; r++) {
        int e = e0 + ty + r * 8;
        float v = tile[tx][ty + r * 8];
        size_t idx = (size_t)b * E_ * DM_ + (size_t)e * DM_ + d0 + tx;
        g_s[idx]  = v;
        g_sq[idx] = tf32q(v);
    }
}

// ---------------- 2. LayerNorm (tf32-rounded output) -------------------------
__global__ void k_layernorm(const float* __restrict__ ln_g, const float* __restrict__ ln_b) {
    int row = blockIdx.x;
    const float* src = g_s + (size_t)row * DM_;
    int tid = threadIdx.x;
    float2 v = ((const float2*)src)[tid];
    float s1 = v.x + v.y;
    float s2 = v.x * v.x + v.y * v.y;
#pragma unroll
    for (int o = 16; o; o >>= 1) {
        s1 += __shfl_xor_sync(0xffffffff, s1, o);
        s2 += __shfl_xor_sync(0xffffffff, s2, o);
    }
    __shared__ float sh[16];
    __shared__ float s_mu, s_rstd;
    int w = tid >> 5, l = tid & 31;
    if (l == 0) { sh[w] = s1; sh[8 + w] = s2; }
    __syncthreads();
    if (tid == 0) {
        float a = 0.f, c = 0.f;
#pragma unroll
        for (int i = 0; i < 8; i++) { a += sh[i]; c += sh[8 + i]; }
        float mu  = a / (float)DM_;
        float var = c / (float)DM_ - mu * mu;
        s_mu = mu;
        s_rstd = 1.f / sqrtf(var + 1e-6f);
    }
    __syncthreads();
    float mu = s_mu, rstd = s_rstd;
    float2 gg = ((const float2*)ln_g)[tid];
    float2 bb = ((const float2*)ln_b)[tid];
    float2 o;
    o.x = tf32q((v.x - mu) * rstd * gg.x + bb.x);
    o.y = tf32q((v.y - mu) * rstd * gg.y + bb.y);
    ((float2*)(g_qn + (size_t)row * DM_))[tid] = o;
}

// ---------------- 3. pack dist -> int8 + quantize weights --------------------
__global__ void k_pack_prep(const int* __restrict__ dist,
                            const float* __restrict__ w_q,
                            const float* __restrict__ w_k,
                            const float* __restrict__ w_v,
                            const float* __restrict__ w_fc) {
    int bid = blockIdx.x;
    if (bid < 2048) {
        int idx = bid * 256 + threadIdx.x;
        int4 v = ((const int4*)dist)[idx];
        uchar4 o;
        o.x = (unsigned char)(v.x > 7 ? 7 : v.x);
        o.y = (unsigned char)(v.y > 7 ? 7 : v.y);
        o.z = (unsigned char)(v.z > 7 ? 7 : v.z);
        o.w = (unsigned char)(v.w > 7 ? 7 : v.w);
        ((uchar4*)g_d8)[idx] = o;
    } else {
        int idx = (bid - 2048) * 256 + threadIdx.x;
        int matid = idx >> 16;
        int off = idx & 65535;
        const float* src = (matid == 0) ? w_q : (matid == 1) ? w_k
                          : (matid == 2) ? w_v : w_fc;
        float4 v = tf32q4(((const float4*)src)[off]);
        float* dst = (matid < 3) ? (g_wq + (size_t)matid * DM_ * 512)
                                 : g_wfcq;
        ((float4*)dst)[off] = v;
    }
}

// ---------------- 4. fused QKV GEMM (r11 proven version) ---------------------
#define QKV_SM 13824
__global__ __launch_bounds__(256) void k_qkv_mma() {
    extern __shared__ float qsm[];
    float* Ab[2] = { qsm, qsm + 4608 };
    float* Wb[2] = { qsm + 9216, qsm + 11520 };
    unsigned a_u[2] = { (unsigned)__cvta_generic_to_shared(Ab[0]),
                        (unsigned)__cvta_generic_to_shared(Ab[1]) };
    unsigned w_u[2] = { (unsigned)__cvta_generic_to_shared(Wb[0]),
                        (unsigned)__cvta_generic_to_shared(Wb[1]) };

    int mat = blockIdx.y >> 3, h = blockIdx.y & 7, b = blockIdx.z;
    int m0 = blockIdx.x * 128;
    const float* A = (mat == 0) ? g_qn : g_sq;
    const float* W = g_wq + (size_t)mat * DM_ * 512;
    float* out = (mat == 0) ? g_q : (mat == 1 ? g_k : g_v);
    float scale = (mat == 0) ? 0.125f : 1.0f;

    int tid = threadIdx.x;
    int wid = tid >> 5, lane = tid & 31;
    int g = lane >> 2, t = lane & 3;
    int warpM = wid & 3, warpN = wid >> 2;

    float acc[2][4][4] = {};
    size_t arow_base = ((size_t)b * E_ + m0);

    {
#pragma unroll
        for (int i = 0; i < 4; i++) {
            int f = tid + i * 256;
            int row = f >> 3, c4 = (f & 7) * 4;
            CP_ASYNC16(a_u[0] + (unsigned)(row * 36 + c4) * 4,
                       A + (arow_base + row) * DM_ + c4);
        }
#pragma unroll
        for (int i = 0; i < 2; i++) {
            int f = tid + i * 256;
            int row = f >> 4, c4 = (f & 15) * 4;
            CP_ASYNC16(w_u[0] + (unsigned)(row * 72 + c4) * 4,
                       W + (size_t)row * 512 + h * 64 + c4);
        }
        CP_COMMIT;
    }
    int cur = 0;
    for (int k0 = 0; k0 < DM_; k0 += 32) {
        CP_WAIT0;
        __syncthreads();
        if (k0 + 32 < DM_) {
            unsigned au = a_u[cur ^ 1], wu = w_u[cur ^ 1];
#pragma unroll
            for (int i = 0; i < 4; i++) {
                int f = tid + i * 256;
                int row = f >> 3, c4 = (f & 7) * 4;
                CP_ASYNC16(au + (unsigned)(row * 36 + c4) * 4,
                           A + (arow_base + row) * DM_ + k0 + 32 + c4);
            }
#pragma unroll
            for (int i = 0; i < 2; i++) {
                int f = tid + i * 256;
                int row = f >> 4, c4 = (f & 15) * 4;
                CP_ASYNC16(wu + (unsigned)(row * 72 + c4) * 4,
                           W + (size_t)(k0 + 32 + row) * 512 + h * 64 + c4);
            }
            CP_COMMIT;
        }
        const unsigned* Asu = (const unsigned*)Ab[cur];
        const unsigned* Wsu = (const unsigned*)Wb[cur];
#pragma unroll
        for (int kk = 0; kk < 4; kk++) {
            int k = kk * 8;
            unsigned af[2][4], bf[4][2];
#pragma unroll
            for (int mb = 0; mb < 2; mb++) {
                int rb = warpM * 32 + mb * 16;
                af[mb][0] = Asu[(rb + g) * 36 + k + t];
                af[mb][1] = Asu[(rb + g + 8) * 36 + k + t];
                af[mb][2] = Asu[(rb + g) * 36 + k + t + 4];
                af[mb][3] = Asu[(rb + g + 8) * 36 + k + t + 4];
            }
#pragma unroll
            for (int nb = 0; nb < 4; nb++) {
                int cb = warpN * 32 + nb * 8 + g;
                bf[nb][0] = Wsu[(k + t) * 72 + cb];
                bf[nb][1] = Wsu[(k + t + 4) * 72 + cb];
            }
#pragma unroll
            for (int mb = 0; mb < 2; mb++)
#pragma unroll
                for (int nb = 0; nb < 4; nb++) MMA8(acc[mb][nb], af[mb], bf[nb])
        }
        cur ^= 1;
    }
    size_t obase = (((size_t)b * H_ + h) * E_ + m0) * 64;
#pragma unroll
    for (int mb = 0; mb < 2; mb++) {
        int r0 = warpM * 32 + mb * 16 + g;
#pragma unroll
        for (int nb = 0; nb < 4; nb++) {
            int c = warpN * 32 + nb * 8 + 2 * t;
            *(float2*)(out + obase + (size_t)r0 * 64 + c) =
                make_float2(tf32q(acc[mb][nb][0] * scale), tf32q(acc[mb][nb][1] * scale));
            *(float2*)(out + obase + (size_t)(r0 + 8) * 64 + c) =
                make_float2(tf32q(acc[mb][nb][2] * scale), tf32q(acc[mb][nb][3] * scale));
        }
    }
}

// ---------------- 5. flash (no-max, separate P buffer, 2 syncs/tile) ---------
// grid (16, B*H): block owns 64 i-rows. warps: 4(warpM,16rows) x 2(warpN,32cols).
#define SM_QS    0
#define SM_K0    4352
#define SM_K1    8704
#define SM_V0    13056
#define SM_V1    17664
#define SM_P     22272
#define SM_RPR   26624
#define SM_QRS   27008
#define SM_ROWL  27392
#define SM_LINV  27520
#define SM_TOTAL 27584   // floats -> 110336 bytes

__global__ __launch_bounds__(256, 2) void k_flash(
    const float* __restrict__ base_rpr, float* __restrict__ attn)
{
    extern __shared__ float sm[];
    float* Qs     = sm + SM_QS;
    float* Ps     = sm + SM_P;
    float* rpr_s  = sm + SM_RPR;
    float* qrs    = sm + SM_QRS;
    float* rowl   = sm + SM_ROWL;
    float* linv_s = sm + SM_LINV;
    float* Kb[2] = { sm + SM_K0, sm + SM_K1 };
    float* Vb[2] = { sm + SM_V0, sm + SM_V1 };
    unsigned k_u[2] = { (unsigned)__cvta_generic_to_shared(Kb[0]),
                        (unsigned)__cvta_generic_to_shared(Kb[1]) };
    unsigned v_u[2] = { (unsigned)__cvta_generic_to_shared(Vb[0]),
                        (unsigned)__cvta_generic_to_shared(Vb[1]) };

    int iblk = blockIdx.x, i0 = iblk * 64;
    int z = blockIdx.y, b = z >> 3;
    int tid = threadIdx.x, wid = tid >> 5, lane = tid & 31;
    int g = lane >> 2, t = lane & 3;
    int warpM = wid & 3, warpN = wid >> 2;

    const unsigned* Qsu = (const unsigned*)Qs;
    const unsigned* Psu = (const unsigned*)Ps;

    size_t qbase = ((size_t)z * E_ + i0) * 64;
    size_t kvbase = (size_t)z * E_ * 64;
    const unsigned char* dbase = g_d8 + (size_t)b * E_ * E_;
    float* abase = attn + (size_t)z * E_ * E_;

#pragma unroll
    for (int i = 0; i < 4; i++) {
        int f = tid + i * 256;
        int row = f >> 4, c4 = (f & 15) * 4;
        *(float4*)&Qs[row * 68 + c4] =
            *(const float4*)(g_q + qbase + (size_t)row * 64 + c4);
    }
    for (int tt = tid; tt < 384; tt += 256) rpr_s[tt] = tf32q(base_rpr[tt]);

    {
        const float* kg = g_k + kvbase;
        const float* vg = g_v + kvbase;
#pragma unroll
        for (int i = 0; i < 4; i++) {
            int f = tid + i * 256;
            int row = f >> 4, c4 = (f & 15) * 4;
            CP_ASYNC16(k_u[0] + (unsigned)(row * 68 + c4) * 4, kg + row * 64 + c4);
            CP_ASYNC16(v_u[0] + (unsigned)(row * 72 + c4) * 4, vg + row * 64 + c4);
        }
        CP_COMMIT;
    }
    __syncthreads();
    for (int tt = tid; tt < 384; tt += 256) {
        int row = tt / 6, c = tt % 6;
        float s = 0.f;
#pragma unroll 16
        for (int d = 0; d < 64; d++) s += Qs[row * 68 + d] * rpr_s[c * 64 + d];
        qrs[tt] = s;
    }

    int il0 = warpM * 16 + g, il1 = il0 + 8;
    int gi0 = i0 + il0, gi1 = i0 + il1;

    float l[2] = {0.f, 0.f};
    float oacc[4][4] = {};
    int cur = 0;

    for (int jt = 0; jt < 16; jt++) {
        int j0 = jt * 64;
        CP_WAIT0;
        __syncthreads();              // buf[cur] ready; prev PV done with Ps
        if (jt < 15) {
            const float* kg = g_k + kvbase + (size_t)(j0 + 64) * 64;
            const float* vg = g_v + kvbase + (size_t)(j0 + 64) * 64;
            unsigned kb = k_u[cur ^ 1], vb = v_u[cur ^ 1];
#pragma unroll
            for (int i = 0; i < 4; i++) {
                int f = tid + i * 256;
                int row = f >> 4, c4 = (f & 15) * 4;
                CP_ASYNC16(kb + (unsigned)(row * 68 + c4) * 4, kg + row * 64 + c4);
                CP_ASYNC16(vb + (unsigned)(row * 72 + c4) * 4, vg + row * 64 + c4);
            }
            CP_COMMIT;
        }
        const unsigned* Ksu = (const unsigned*)Kb[cur];
        const unsigned* Vsu = (const unsigned*)Vb[cur];
        // QK mma
        float acc[4][4] = {};
#pragma unroll
        for (int kk = 0; kk < 8; kk++) {
            int k = kk * 8;
            unsigned af[4];
            int rb = warpM * 16;
            af[0] = Qsu[(rb + g) * 68 + k + t];
            af[1] = Qsu[(rb + g + 8) * 68 + k + t];
            af[2] = Qsu[(rb + g) * 68 + k + t + 4];
            af[3] = Qsu[(rb + g + 8) * 68 + k + t + 4];
#pragma unroll
            for (int nb = 0; nb < 4; nb++) {
                unsigned bf[2];
                int cb = warpN * 32 + nb * 8 + g;
                bf[0] = Ksu[cb * 68 + k + t];
                bf[1] = Ksu[cb * 68 + k + t + 4];
                MMA8(acc[nb], af, bf)
            }
        }
        // p = exp(x) (masked -> 0): write attn + Ps immediately (short liveness)
#pragma unroll
        for (int nb = 0; nb < 4; nb++) {
            int jl = warpN * 32 + nb * 8 + 2 * t;
            int j = j0 + jl;
            uchar2 d0 = *(const uchar2*)(dbase + (size_t)gi0 * E_ + j);
            uchar2 d1 = *(const uchar2*)(dbase + (size_t)gi1 * E_ + j);
            float p00 = (d0.x <= MAXN_) ? __expf(acc[nb][0] + qrs[il0 * 6 + d0.x]) : 0.f;
            float p01 = (d0.y <= MAXN_) ? __expf(acc[nb][1] + qrs[il0 * 6 + d0.y]) : 0.f;
            float p10 = (d1.x <= MAXN_) ? __expf(acc[nb][2] + qrs[il1 * 6 + d1.x]) : 0.f;
            float p11 = (d1.y <= MAXN_) ? __expf(acc[nb][3] + qrs[il1 * 6 + d1.y]) : 0.f;
            l[0] += p00 + p01;
            l[1] += p10 + p11;
            *(float2*)(abase + (size_t)gi0 * E_ + j) = make_float2(p00, p01);
            *(float2*)(abase + (size_t)gi1 * E_ + j) = make_float2(p10, p11);
            Ps[il0 * 68 + jl]     = tf32q(p00);
            Ps[il0 * 68 + jl + 1] = tf32q(p01);
            Ps[il1 * 68 + jl]     = tf32q(p10);
            Ps[il1 * 68 + jl + 1] = tf32q(p11);
        }
        __syncthreads();              // Ps complete
        // O += P(64x64) @ V(64x64)
#pragma unroll
        for (int kk = 0; kk < 8; kk++) {
            int k = kk * 8;
            unsigned af[4];
            int rb = warpM * 16;
            af[0] = Psu[(rb + g) * 68 + k + t];
            af[1] = Psu[(rb + g + 8) * 68 + k + t];
            af[2] = Psu[(rb + g) * 68 + k + t + 4];
            af[3] = Psu[(rb + g + 8) * 68 + k + t + 4];
#pragma unroll
            for (int nb = 0; nb < 4; nb++) {
                unsigned bf[2];
                int cb = warpN * 32 + nb * 8 + g;
                bf[0] = Vsu[(k + t) * 72 + cb];
                bf[1] = Vsu[(k + t + 4) * 72 + cb];
                MMA8(oacc[nb], af, bf)
            }
        }
        cur ^= 1;
    }
    // reduce l over t lanes + 2 warpN warps
#pragma unroll
    for (int off = 1; off < 4; off <<= 1) {
        l[0] += __shfl_xor_sync(0xffffffff, l[0], off);
        l[1] += __shfl_xor_sync(0xffffffff, l[1], off);
    }
    if (t == 0) {
        rowl[il0 * 2 + warpN] = l[0];
        rowl[il1 * 2 + warpN] = l[1];
    }
    __syncthreads();
    if (tid < 64) linv_s[tid] = 1.f / (rowl[tid * 2] + rowl[tid * 2 + 1]);
    __syncthreads();
    float inv0 = linv_s[il0], inv1 = linv_s[il1];
    int h = z & 7;
#pragma unroll
    for (int nb = 0; nb < 4; nb++) {
        int dv = h * 64 + warpN * 32 + nb * 8 + 2 * t;
        *(float2*)(g_o + ((size_t)b * E_ + gi0) * 512 + dv) =
            make_float2(tf32q(oacc[nb][0] * inv0), tf32q(oacc[nb][1] * inv0));
        *(float2*)(g_o + ((size_t)b * E_ + gi1) * 512 + dv) =
            make_float2(tf32q(oacc[nb][2] * inv1), tf32q(oacc[nb][3] * inv1));
    }
    // fused fixup: rescale own rows by 1/l (L2-hot) + ape column partials
    {
        int j = tid * 4;
        float4 cs = make_float4(0.f, 0.f, 0.f, 0.f);
        float* arow = abase + (size_t)i0 * E_ + j;
#pragma unroll 4
        for (int r = 0; r < 64; r++) {
            float fac = linv_s[r];
            float4 x = *(float4*)(arow + (size_t)r * E_);
            x.x *= fac; x.y *= fac; x.z *= fac; x.w *= fac;
            *(float4*)(arow + (size_t)r * E_) = x;
            cs.x += x.x; cs.y += x.y; cs.z += x.z; cs.w += x.w;
        }
        *(float4*)(g_pcs2 + ((size_t)z * 16 + iblk) * E_ + j) = cs;
    }
}

// ---------------- 6. FC + residual (cp.async double-buffered) ----------------
#define FC_SM 13824
__global__ __launch_bounds__(256) void k_fc_mma(float* __restrict__ xout) {
    extern __shared__ float fsm[];
    float* Ab[2] = { fsm, fsm + 4608 };
    float* Wb[2] = { fsm + 9216, fsm + 11520 };
    unsigned a_u[2] = { (unsigned)__cvta_generic_to_shared(Ab[0]),
                        (unsigned)__cvta_generic_to_shared(Ab[1]) };
    unsigned w_u[2] = { (unsigned)__cvta_generic_to_shared(Wb[0]),
                        (unsigned)__cvta_generic_to_shared(Wb[1]) };
    int m0 = blockIdx.x * 128, n0 = blockIdx.y * 64;
    int b = m0 >> 10, e0 = m0 & 1023;
    int tid = threadIdx.x;
    int wid = tid >> 5, lane = tid & 31;
    int g = lane >> 2, t = lane & 3;
    int warpM = wid & 3, warpN = wid >> 2;

    float acc[2][4][4] = {};

    {
#pragma unroll
        for (int i = 0; i < 4; i++) {
            int f = tid + i * 256;
            int row = f >> 3, c4 = (f & 7) * 4;
            CP_ASYNC16(a_u[0] + (unsigned)(row * 36 + c4) * 4,
                       g_o + (size_t)(m0 + row) * 512 + c4);
        }
#pragma unroll
        for (int i = 0; i < 2; i++) {
            int f = tid + i * 256;
            int row = f >> 4, c4 = (f & 15) * 4;
            CP_ASYNC16(w_u[0] + (unsigned)(row * 72 + c4) * 4,
                       g_wfcq + (size_t)row * 512 + n0 + c4);
        }
        CP_COMMIT;
    }
    int cur = 0;
    for (int k0 = 0; k0 < 512; k0 += 32) {
        CP_WAIT0;
        __syncthreads();
        if (k0 + 32 < 512) {
            unsigned au = a_u[cur ^ 1], wu = w_u[cur ^ 1];
#pragma unroll
            for (int i = 0; i < 4; i++) {
                int f = tid + i * 256;
                int row = f >> 3, c4 = (f & 7) * 4;
                CP_ASYNC16(au + (unsigned)(row * 36 + c4) * 4,
                           g_o + (size_t)(m0 + row) * 512 + k0 + 32 + c4);
            }
#pragma unroll
            for (int i = 0; i < 2; i++) {
                int f = tid + i * 256;
                int row = f >> 4, c4 = (f & 15) * 4;
                CP_ASYNC16(wu + (unsigned)(row * 72 + c4) * 4,
                           g_wfcq + (size_t)(k0 + 32 + row) * 512 + n0 + c4);
            }
            CP_COMMIT;
        }
        const unsigned* Asu = (const unsigned*)Ab[cur];
        const unsigned* Wsu = (const unsigned*)Wb[cur];
#pragma unroll
        for (int kk = 0; kk < 4; kk++) {
            int k = kk * 8;
            unsigned af[2][4], bf[4][2];
#pragma unroll
            for (int mb = 0; mb < 2; mb++) {
                int rb = warpM * 32 + mb * 16;
                af[mb][0] = Asu[(rb + g) * 36 + k + t];
                af[mb][1] = Asu[(rb + g + 8) * 36 + k + t];
                af[mb][2] = Asu[(rb + g) * 36 + k + t + 4];
                af[mb][3] = Asu[(rb + g + 8) * 36 + k + t + 4];
            }
#pragma unroll
            for (int nb = 0; nb < 4; nb++) {
                int cb = warpN * 32 + nb * 8 + g;
                bf[nb][0] = Wsu[(k + t) * 72 + cb];
                bf[nb][1] = Wsu[(k + t + 4) * 72 + cb];
            }
#pragma unroll
            for (int mb = 0; mb < 2; mb++)
#pragma unroll
                for (int nb = 0; nb < 4; nb++) MMA8(acc[mb][nb], af[mb], bf[nb])
        }
        cur ^= 1;
    }
    __syncthreads();
#pragma unroll
    for (int mb = 0; mb < 2; mb++) {
        int el0 = warpM * 32 + mb * 16 + g;
#pragma unroll
        for (int nb = 0; nb < 4; nb++) {
            int nl = warpN * 32 + nb * 8 + 2 * t;
#pragma unroll
            for (int half = 0; half < 2; half++) {
                int el = el0 + half * 8;
                const float* res = g_s + (size_t)(m0 + el) * DM_ + n0 + nl;
                fsm[(nl + 0) * 132 + el] = acc[mb][nb][half * 2 + 0] + res[0];
                fsm[(nl + 1) * 132 + el] = acc[mb][nb][half * 2 + 1] + res[1];
            }
        }
    }
    __syncthreads();
#pragma unroll
    for (int i = 0; i < 8; i++) {
        int f = tid + i * 256;
        int row = f >> 5, c4 = (f & 31) * 4;
        float4 v = *(const float4*)&fsm[row * 132 + c4];
        *(float4*)(xout + ((size_t)b * DM_ + n0 + row) * E_ + e0 + c4) = v;
    }
}

// ---------------- 7. ape final -------------------------------------------------
__global__ void k_ape_final(float* __restrict__ ape) {
    int idx = blockIdx.x * 256 + threadIdx.x;
    int b = idx >> 10, j = idx & (E_ - 1);
    float cs = 0.f;
    const float* p = g_pcs2 + (size_t)b * 8 * 16 * E_ + j;
#pragma unroll 8
    for (int k = 0; k < 128; k++) cs += p[(size_t)k * E_];
    const unsigned char* dcol = g_d8 + (size_t)b * E_ * E_ + j;
    int cnt = 0;
#pragma unroll 8
    for (int i = 0; i < E_; i++) cnt += (dcol[(size_t)i * E_] <= MAXN_) ? 1 : 0;
    ape[idx] = cs / (float)cnt;
}

// ---------------- launch ------------------------------------------------------
extern "C" void kernel_launch(void* const* d_in, const int* in_sizes, int n_in,
                              void* d_out, int out_size) {
    const float* x        = (const float*)d_in[0];
    const int*   dist     = (const int*)  d_in[1];
    const float* base_rpr = (const float*)d_in[2];
    const float* w_q      = (const float*)d_in[3];
    const float* w_k      = (const float*)d_in[4];
    const float* w_v      = (const float*)d_in[5];
    const float* w_fc     = (const float*)d_in[6];
    const float* ln_g     = (const float*)d_in[7];
    const float* ln_b     = (const float*)d_in[8];

    float* x_out = (float*)d_out;
    float* attn  = x_out + (size_t)B_ * DM_ * E_;
    float* ape   = attn  + (size_t)B_ * H_ * E_ * E_;

    static int smem_set = 0;
    if (!smem_set) {
        cudaFuncSetAttribute(k_flash, cudaFuncAttributeMaxDynamicSharedMemorySize,
                             SM_TOTAL * 4);
        cudaFuncSetAttribute(k_qkv_mma, cudaFuncAttributeMaxDynamicSharedMemorySize,
                             QKV_SM * 4);
        cudaFuncSetAttribute(k_fc_mma, cudaFuncAttributeMaxDynamicSharedMemorySize,
                             FC_SM * 4);
        smem_set = 1;
    }

    k_transpose<<<dim3(E_ / 32, DM_ / 32, B_), dim3(32, 8)>>>(x);
    k_layernorm<<<B_ * E_, 256>>>(ln_g, ln_b);
    k_pack_prep<<<3072, 256>>>(dist, w_q, w_k, w_v, w_fc);

    k_qkv_mma<<<dim3(E_ / 128, 24, B_), 256, QKV_SM * 4>>>();

    k_flash<<<dim3(16, B_ * H_), 256, SM_TOTAL * 4>>>(base_rpr, attn);
    k_fc_mma<<<dim3(B_ * E_ / 128, DM_ / 64, 1), 256, FC_SM * 4>>>(x_out);
    k_ape_final<<<(B_ * E_) / 256, 256>>>(ape);
}

// round 15
// speedup vs baseline: 1.1624x; 1.0940x over previous
#include <cuda_runtime.h>
#include <cuda_bf16.h>
#include <math.h>

#define B_  2
#define E_  1024
#define DM_ 512
#define H_  8
#define DK_ 64
#define DV_ 64
#define MAXN_ 5

__device__ __forceinline__ float tf32q(float x) {
    unsigned u;
    asm("cvt.rna.tf32.f32 %0, %1;" : "=r"(u) : "f"(x));
    return __uint_as_float(u);
}
__device__ __forceinline__ float4 tf32q4(float4 v) {
    v.x = tf32q(v.x); v.y = tf32q(v.y); v.z = tf32q(v.z); v.w = tf32q(v.w);
    return v;
}

// tf32: D(16x8) += A(16x8) * B(8x8)
#define MMA8(d, a, b)                                                        \
    asm volatile(                                                            \
        "mma.sync.aligned.m16n8k8.row.col.f32.tf32.tf32.f32 "                \
        "{%0,%1,%2,%3}, {%4,%5,%6,%7}, {%8,%9}, {%0,%1,%2,%3};\n"            \
        : "+f"((d)[0]), "+f"((d)[1]), "+f"((d)[2]), "+f"((d)[3])             \
        : "r"((a)[0]), "r"((a)[1]), "r"((a)[2]), "r"((a)[3]),                \
          "r"((b)[0]), "r"((b)[1]));

// bf16: D(16x8) += A(16x16) * B(16x8)
#define MMA16(d, a, b)                                                       \
    asm volatile(                                                            \
        "mma.sync.aligned.m16n8k16.row.col.f32.bf16.bf16.f32 "               \
        "{%0,%1,%2,%3}, {%4,%5,%6,%7}, {%8,%9}, {%0,%1,%2,%3};\n"            \
        : "+f"((d)[0]), "+f"((d)[1]), "+f"((d)[2]), "+f"((d)[3])             \
        : "r"((a)[0]), "r"((a)[1]), "r"((a)[2]), "r"((a)[3]),                \
          "r"((b)[0]), "r"((b)[1]));

#define CP_ASYNC16(su, gp)                                                   \
    asm volatile("cp.async.cg.shared.global [%0], [%1], 16;\n"               \
                 :: "r"(su), "l"(gp) : "memory")
#define CP_COMMIT  asm volatile("cp.async.commit_group;\n" ::: "memory")
#define CP_WAIT0   asm volatile("cp.async.wait_group 0;\n" ::: "memory")

// ---------------- scratch ---------------------------------------------------
__device__ float g_s  [B_*E_*DM_];            // exact (LN stats + FC residual)
__device__ float g_sq [B_*E_*DM_];            // tf32-rounded (K/V GEMM input)
__device__ float g_qn [B_*E_*DM_];            // LN output, tf32-rounded
__device__ __nv_bfloat16 g_q16[B_*H_*E_*DK_]; // bf16 (scaled 1/8)
__device__ __nv_bfloat16 g_k16[B_*H_*E_*DK_]; // bf16
__device__ float g_v  [B_*H_*E_*DV_];         // tf32-rounded
__device__ float g_o  [B_*E_*H_*DV_];         // tf32-rounded
__device__ float g_wq  [3*DM_*(H_*DK_)];      // quantized w_q|w_k|w_v
__device__ float g_wfcq[DM_*DM_];             // quantized w_fc
__device__ float g_pcs2[B_*H_*16*E_];
__device__ unsigned char g_d8[B_*E_*E_];

// ---------------- 1. transpose x[b,d,e] -> s[b,e,d] (+tf32 copy) ------------
__global__ void k_transpose(const float* __restrict__ x) {
    __shared__ float tile[32][33];
    int b = blockIdx.z;
    int e0 = blockIdx.x * 32;
    int d0 = blockIdx.y * 32;
    int tx = threadIdx.x, ty = threadIdx.y;
#pragma unroll
    for (int r = 0; r < 4; r++) {
        int d = d0 + ty + r * 8;
        tile[ty + r * 8][tx] = x[(size_t)b * DM_ * E_ + (size_t)d * E_ + e0 + tx];
    }
    __syncthreads();
#pragma unroll
    for (int r = 0; r < 4; r++) {
        int e = e0 + ty + r * 8;
        float v = tile[tx][ty + r * 8];
        size_t idx = (size_t)b * E_ * DM_ + (size_t)e * DM_ + d0 + tx;
        g_s[idx]  = v;
        g_sq[idx] = tf32q(v);
    }
}

// ---------------- 2. LayerNorm (tf32-rounded output) -------------------------
__global__ void k_layernorm(const float* __restrict__ ln_g, const float* __restrict__ ln_b) {
    int row = blockIdx.x;
    const float* src = g_s + (size_t)row * DM_;
    int tid = threadIdx.x;
    float2 v = ((const float2*)src)[tid];
    float s1 = v.x + v.y;
    float s2 = v.x * v.x + v.y * v.y;
#pragma unroll
    for (int o = 16; o; o >>= 1) {
        s1 += __shfl_xor_sync(0xffffffff, s1, o);
        s2 += __shfl_xor_sync(0xffffffff, s2, o);
    }
    __shared__ float sh[16];
    __shared__ float s_mu, s_rstd;
    int w = tid >> 5, l = tid & 31;
    if (l == 0) { sh[w] = s1; sh[8 + w] = s2; }
    __syncthreads();
    if (tid == 0) {
        float a = 0.f, c = 0.f;
#pragma unroll
        for (int i = 0; i < 8; i++) { a += sh[i]; c += sh[8 + i]; }
        float mu  = a / (float)DM_;
        float var = c / (float)DM_ - mu * mu;
        s_mu = mu;
        s_rstd = 1.f / sqrtf(var + 1e-6f);
    }
    __syncthreads();
    float mu = s_mu, rstd = s_rstd;
    float2 gg = ((const float2*)ln_g)[tid];
    float2 bb = ((const float2*)ln_b)[tid];
    float2 o;
    o.x = tf32q((v.x - mu) * rstd * gg.x + bb.x);
    o.y = tf32q((v.y - mu) * rstd * gg.y + bb.y);
    ((float2*)(g_qn + (size_t)row * DM_))[tid] = o;
}

// ---------------- 3. pack dist -> int8 + quantize weights --------------------
__global__ void k_pack_prep(const int* __restrict__ dist,
                            const float* __restrict__ w_q,
                            const float* __restrict__ w_k,
                            const float* __restrict__ w_v,
                            const float* __restrict__ w_fc) {
    int bid = blockIdx.x;
    if (bid < 2048) {
        int idx = bid * 256 + threadIdx.x;
        int4 v = ((const int4*)dist)[idx];
        uchar4 o;
        o.x = (unsigned char)(v.x > 7 ? 7 : v.x);
        o.y = (unsigned char)(v.y > 7 ? 7 : v.y);
        o.z = (unsigned char)(v.z > 7 ? 7 : v.z);
        o.w = (unsigned char)(v.w > 7 ? 7 : v.w);
        ((uchar4*)g_d8)[idx] = o;
    } else {
        int idx = (bid - 2048) * 256 + threadIdx.x;
        int matid = idx >> 16;
        int off = idx & 65535;
        const float* src = (matid == 0) ? w_q : (matid == 1) ? w_k
                          : (matid == 2) ? w_v : w_fc;
        float4 v = tf32q4(((const float4*)src)[off]);
        float* dst = (matid < 3) ? (g_wq + (size_t)matid * DM_ * 512)
                                 : g_wfcq;
        ((float4*)dst)[off] = v;
    }
}

// ---------------- 4. fused QKV GEMM (Q/K -> bf16, V -> tf32 fp32) ------------
#define QKV_SM 13824
__global__ __launch_bounds__(256) void k_qkv_mma() {
    extern __shared__ float qsm[];
    float* Ab[2] = { qsm, qsm + 4608 };
    float* Wb[2] = { qsm + 9216, qsm + 11520 };
    unsigned a_u[2] = { (unsigned)__cvta_generic_to_shared(Ab[0]),
                        (unsigned)__cvta_generic_to_shared(Ab[1]) };
    unsigned w_u[2] = { (unsigned)__cvta_generic_to_shared(Wb[0]),
                        (unsigned)__cvta_generic_to_shared(Wb[1]) };

    int mat = blockIdx.y >> 3, h = blockIdx.y & 7, b = blockIdx.z;
    int m0 = blockIdx.x * 128;
    const float* A = (mat == 0) ? g_qn : g_sq;
    const float* W = g_wq + (size_t)mat * DM_ * 512;
    float scale = (mat == 0) ? 0.125f : 1.0f;

    int tid = threadIdx.x;
    int wid = tid >> 5, lane = tid & 31;
    int g = lane >> 2, t = lane & 3;
    int warpM = wid & 3, warpN = wid >> 2;

    float acc[2][4][4] = {};
    size_t arow_base = ((size_t)b * E_ + m0);

    {
#pragma unroll
        for (int i = 0; i < 4; i++) {
            int f = tid + i * 256;
            int row = f >> 3, c4 = (f & 7) * 4;
            CP_ASYNC16(a_u[0] + (unsigned)(row * 36 + c4) * 4,
                       A + (arow_base + row) * DM_ + c4);
        }
#pragma unroll
        for (int i = 0; i < 2; i++) {
            int f = tid + i * 256;
            int row = f >> 4, c4 = (f & 15) * 4;
            CP_ASYNC16(w_u[0] + (unsigned)(row * 72 + c4) * 4,
                       W + (size_t)row * 512 + h * 64 + c4);
        }
        CP_COMMIT;
    }
    int cur = 0;
    for (int k0 = 0; k0 < DM_; k0 += 32) {
        CP_WAIT0;
        __syncthreads();
        if (k0 + 32 < DM_) {
            unsigned au = a_u[cur ^ 1], wu = w_u[cur ^ 1];
#pragma unroll
            for (int i = 0; i < 4; i++) {
                int f = tid + i * 256;
                int row = f >> 3, c4 = (f & 7) * 4;
                CP_ASYNC16(au + (unsigned)(row * 36 + c4) * 4,
                           A + (arow_base + row) * DM_ + k0 + 32 + c4);
            }
#pragma unroll
            for (int i = 0; i < 2; i++) {
                int f = tid + i * 256;
                int row = f >> 4, c4 = (f & 15) * 4;
                CP_ASYNC16(wu + (unsigned)(row * 72 + c4) * 4,
                           W + (size_t)(k0 + 32 + row) * 512 + h * 64 + c4);
            }
            CP_COMMIT;
        }
        const unsigned* Asu = (const unsigned*)Ab[cur];
        const unsigned* Wsu = (const unsigned*)Wb[cur];
#pragma unroll
        for (int kk = 0; kk < 4; kk++) {
            int k = kk * 8;
            unsigned af[2][4], bf[4][2];
#pragma unroll
            for (int mb = 0; mb < 2; mb++) {
                int rb = warpM * 32 + mb * 16;
                af[mb][0] = Asu[(rb + g) * 36 + k + t];
                af[mb][1] = Asu[(rb + g + 8) * 36 + k + t];
                af[mb][2] = Asu[(rb + g) * 36 + k + t + 4];
                af[mb][3] = Asu[(rb + g + 8) * 36 + k + t + 4];
            }
#pragma unroll
            for (int nb = 0; nb < 4; nb++) {
                int cb = warpN * 32 + nb * 8 + g;
                bf[nb][0] = Wsu[(k + t) * 72 + cb];
                bf[nb][1] = Wsu[(k + t + 4) * 72 + cb];
            }
#pragma unroll
            for (int mb = 0; mb < 2; mb++)
#pragma unroll
                for (int nb = 0; nb < 4; nb++) MMA8(acc[mb][nb], af[mb], bf[nb])
        }
        cur ^= 1;
    }
    size_t obase = (((size_t)b * H_ + h) * E_ + m0) * 64;
    if (mat == 2) {
#pragma unroll
        for (int mb = 0; mb < 2; mb++) {
            int r0 = warpM * 32 + mb * 16 + g;
#pragma unroll
            for (int nb = 0; nb < 4; nb++) {
                int c = warpN * 32 + nb * 8 + 2 * t;
                *(float2*)(g_v + obase + (size_t)r0 * 64 + c) =
                    make_float2(tf32q(acc[mb][nb][0]), tf32q(acc[mb][nb][1]));
                *(float2*)(g_v + obase + (size_t)(r0 + 8) * 64 + c) =
                    make_float2(tf32q(acc[mb][nb][2]), tf32q(acc[mb][nb][3]));
            }
        }
    } else {
        __nv_bfloat16* o16 = (mat == 0) ? g_q16 : g_k16;
#pragma unroll
        for (int mb = 0; mb < 2; mb++) {
            int r0 = warpM * 32 + mb * 16 + g;
#pragma unroll
            for (int nb = 0; nb < 4; nb++) {
                int c = warpN * 32 + nb * 8 + 2 * t;
                __nv_bfloat162 h0, h1;
                h0.x = __float2bfloat16(acc[mb][nb][0] * scale);
                h0.y = __float2bfloat16(acc[mb][nb][1] * scale);
                h1.x = __float2bfloat16(acc[mb][nb][2] * scale);
                h1.y = __float2bfloat16(acc[mb][nb][3] * scale);
                *(__nv_bfloat162*)(o16 + obase + (size_t)r0 * 64 + c) = h0;
                *(__nv_bfloat162*)(o16 + obase + (size_t)(r0 + 8) * 64 + c) = h1;
            }
        }
    }
}

// ---------------- 5. flash: bf16 QK + tf32 PV, dist staged, double-buffered --
// grid (16, B*H): 64 i-rows/block. warps: 4(warpM,16rows) x 2(warpN,32cols).
#define SQ16   0        // Qs16: 64x72 halves = 2304 floats
#define SK0    2304     // K bf16: 64x72 halves = 2304 floats
#define SK1    4608
#define SV0    6912     // V fp32: 64x72 = 4608 floats
#define SV1    11520
#define SPS    16128    // P tf32: 64x68 = 4352 floats
#define SD0    20480    // dist: 64x80 bytes = 1280 floats
#define SD1    21760
#define SRPR   23040
#define SQRS   23424
#define SROWL  23808
#define SLINV  23936
#define SM_TOTAL 24000  // floats -> 96000 bytes

__global__ __launch_bounds__(256, 2) void k_flash(
    const float* __restrict__ base_rpr, float* __restrict__ attn)
{
    extern __shared__ float sm[];
    __nv_bfloat16* Qs16 = (__nv_bfloat16*)(sm + SQ16);
    __nv_bfloat16* Kb16[2] = { (__nv_bfloat16*)(sm + SK0), (__nv_bfloat16*)(sm + SK1) };
    float* Vb[2] = { sm + SV0, sm + SV1 };
    unsigned char* Db[2] = { (unsigned char*)(sm + SD0), (unsigned char*)(sm + SD1) };
    float* Ps     = sm + SPS;
    float* rpr_s  = sm + SRPR;
    float* qrs    = sm + SQRS;
    float* rowl   = sm + SROWL;
    float* linv_s = sm + SLINV;
    unsigned k_u[2] = { (unsigned)__cvta_generic_to_shared(Kb16[0]),
                        (unsigned)__cvta_generic_to_shared(Kb16[1]) };
    unsigned v_u[2] = { (unsigned)__cvta_generic_to_shared(Vb[0]),
                        (unsigned)__cvta_generic_to_shared(Vb[1]) };
    unsigned d_u[2] = { (unsigned)__cvta_generic_to_shared(Db[0]),
                        (unsigned)__cvta_generic_to_shared(Db[1]) };

    int iblk = blockIdx.x, i0 = iblk * 64;
    int z = blockIdx.y, b = z >> 3;
    int tid = threadIdx.x, wid = tid >> 5, lane = tid & 31;
    int g = lane >> 2, t = lane & 3;
    int warpM = wid & 3, warpN = wid >> 2;

    const unsigned* Qsu = (const unsigned*)Qs16;   // stride 36 u32/row
    const unsigned* Psu = (const unsigned*)Ps;

    size_t qbase = ((size_t)z * E_ + i0) * 64;     // halves
    size_t kvbase = (size_t)z * E_ * 64;
    const unsigned char* dgbase = g_d8 + (size_t)b * E_ * E_;
    float* abase = attn + (size_t)z * E_ * E_;

    // prologue: Q bf16 tile, rpr
#pragma unroll
    for (int i = 0; i < 2; i++) {
        int f = tid + i * 256;                     // 512 chunks of 8 halves
        int row = f >> 3, c = f & 7;
        *(uint4*)(Qs16 + row * 72 + c * 8) =
            *(const uint4*)(g_q16 + qbase + (size_t)row * 64 + c * 8);
    }
    for (int tt = tid; tt < 384; tt += 256) rpr_s[tt] = tf32q(base_rpr[tt]);

    // preload tile 0: K(bf16), V(fp32), dist
    {
        const __nv_bfloat16* kg = g_k16 + kvbase;
        const float* vg = g_v + kvbase;
#pragma unroll
        for (int i = 0; i < 2; i++) {
            int f = tid + i * 256;
            int row = f >> 3, c = f & 7;
            CP_ASYNC16(k_u[0] + (unsigned)(row * 144 + c * 16),
                       kg + (size_t)row * 64 + c * 8);
        }
#pragma unroll
        for (int i = 0; i < 4; i++) {
            int f = tid + i * 256;
            int row = f >> 4, c4 = (f & 15) * 4;
            CP_ASYNC16(v_u[0] + (unsigned)(row * 72 + c4) * 4,
                       vg + (size_t)row * 64 + c4);
        }
        {
            int row = tid >> 2, c = tid & 3;
            CP_ASYNC16(d_u[0] + (unsigned)(row * 80 + c * 16),
                       dgbase + (size_t)(i0 + row) * E_ + c * 16);
        }
        CP_COMMIT;
    }
    __syncthreads();
    for (int tt = tid; tt < 384; tt += 256) {
        int row = tt / 6, c = tt % 6;
        float s = 0.f;
#pragma unroll 16
        for (int d = 0; d < 64; d++)
            s += __bfloat162float(Qs16[row * 72 + d]) * rpr_s[c * 64 + d];
        qrs[tt] = s;
    }

    int il0 = warpM * 16 + g, il1 = il0 + 8;
    int gi0 = i0 + il0, gi1 = i0 + il1;

    float l[2] = {0.f, 0.f};
    float oacc[4][4] = {};
    int cur = 0;

    for (int jt = 0; jt < 16; jt++) {
        int j0 = jt * 64;
        CP_WAIT0;
        __syncthreads();              // buf[cur] ready; prev PV done with Ps
        if (jt < 15) {
            const __nv_bfloat16* kg = g_k16 + kvbase + (size_t)(j0 + 64) * 64;
            const float* vg = g_v + kvbase + (size_t)(j0 + 64) * 64;
            unsigned kb = k_u[cur ^ 1], vb = v_u[cur ^ 1], db = d_u[cur ^ 1];
#pragma unroll
            for (int i = 0; i < 2; i++) {
                int f = tid + i * 256;
                int row = f >> 3, c = f & 7;
                CP_ASYNC16(kb + (unsigned)(row * 144 + c * 16),
                           kg + (size_t)row * 64 + c * 8);
            }
#pragma unroll
            for (int i = 0; i < 4; i++) {
                int f = tid + i * 256;
                int row = f >> 4, c4 = (f & 15) * 4;
                CP_ASYNC16(vb + (unsigned)(row * 72 + c4) * 4,
                           vg + (size_t)row * 64 + c4);
            }
            {
                int row = tid >> 2, c = tid & 3;
                CP_ASYNC16(db + (unsigned)(row * 80 + c * 16),
                           dgbase + (size_t)(i0 + row) * E_ + j0 + 64 + c * 16);
            }
            CP_COMMIT;
        }
        const unsigned* Ksu = (const unsigned*)Kb16[cur];   // stride 36 u32/row
        const unsigned* Vsu = (const unsigned*)Vb[cur];
        const unsigned char* Ds = Db[cur];
        // QK mma (bf16, k=16): 4 kk-chunks
        float acc[4][4] = {};
#pragma unroll
        for (int kk = 0; kk < 4; kk++) {
            int k = kk * 8;           // u32 index base = kk*16 halves /2
            unsigned af[4];
            int rb = warpM * 16;
            af[0] = Qsu[(rb + g) * 36 + k + t];
            af[1] = Qsu[(rb + g + 8) * 36 + k + t];
            af[2] = Qsu[(rb + g) * 36 + k + t + 4];
            af[3] = Qsu[(rb + g + 8) * 36 + k + t + 4];
#pragma unroll
            for (int nb = 0; nb < 4; nb++) {
                unsigned bf[2];
                int cb = warpN * 32 + nb * 8 + g;
                bf[0] = Ksu[cb * 36 + k + t];
                bf[1] = Ksu[cb * 36 + k + t + 4];
                MMA16(acc[nb], af, bf)
            }
        }
        // p = exp(x) (masked -> 0): dist from smem; write attn + Ps immediately
#pragma unroll
        for (int nb = 0; nb < 4; nb++) {
            int jl = warpN * 32 + nb * 8 + 2 * t;
            int j = j0 + jl;
            uchar2 d0 = *(const uchar2*)(Ds + il0 * 80 + jl);
            uchar2 d1 = *(const uchar2*)(Ds + il1 * 80 + jl);
            float p00 = (d0.x <= MAXN_) ? __expf(acc[nb][0] + qrs[il0 * 6 + d0.x]) : 0.f;
            float p01 = (d0.y <= MAXN_) ? __expf(acc[nb][1] + qrs[il0 * 6 + d0.y]) : 0.f;
            float p10 = (d1.x <= MAXN_) ? __expf(acc[nb][2] + qrs[il1 * 6 + d1.x]) : 0.f;
            float p11 = (d1.y <= MAXN_) ? __expf(acc[nb][3] + qrs[il1 * 6 + d1.y]) : 0.f;
            l[0] += p00 + p01;
            l[1] += p10 + p11;
            *(float2*)(abase + (size_t)gi0 * E_ + j) = make_float2(p00, p01);
            *(float2*)(abase + (size_t)gi1 * E_ + j) = make_float2(p10, p11);
            Ps[il0 * 68 + jl]     = tf32q(p00);
            Ps[il0 * 68 + jl + 1] = tf32q(p01);
            Ps[il1 * 68 + jl]     = tf32q(p10);
            Ps[il1 * 68 + jl + 1] = tf32q(p11);
        }
        __syncthreads();              // Ps complete
        // O += P(64x64) @ V(64x64)  (tf32)
#pragma unroll
        for (int kk = 0; kk < 8; kk++) {
            int k = kk * 8;
            unsigned af[4];
            int rb = warpM * 16;
            af[0] = Psu[(rb + g) * 68 + k + t];
            af[1] = Psu[(rb + g + 8) * 68 + k + t];
            af[2] = Psu[(rb + g) * 68 + k + t + 4];
            af[3] = Psu[(rb + g + 8) * 68 + k + t + 4];
#pragma unroll
            for (int nb = 0; nb < 4; nb++) {
                unsigned bf[2];
                int cb = warpN * 32 + nb * 8 + g;
                bf[0] = Vsu[(k + t) * 72 + cb];
                bf[1] = Vsu[(k + t + 4) * 72 + cb];
                MMA8(oacc[nb], af, bf)
            }
        }
        cur ^= 1;
    }
    // reduce l over t lanes + 2 warpN warps
#pragma unroll
    for (int off = 1; off < 4; off <<= 1) {
        l[0] += __shfl_xor_sync(0xffffffff, l[0], off);
        l[1] += __shfl_xor_sync(0xffffffff, l[1], off);
    }
    if (t == 0) {
        rowl[il0 * 2 + warpN] = l[0];
        rowl[il1 * 2 + warpN] = l[1];
    }
    __syncthreads();
    if (tid < 64) linv_s[tid] = 1.f / (rowl[tid * 2] + rowl[tid * 2 + 1]);
    __syncthreads();
    float inv0 = linv_s[il0], inv1 = linv_s[il1];
    int h = z & 7;
#pragma unroll
    for (int nb = 0; nb < 4; nb++) {
        int dv = h * 64 + warpN * 32 + nb * 8 + 2 * t;
        *(float2*)(g_o + ((size_t)b * E_ + gi0) * 512 + dv) =
            make_float2(tf32q(oacc[nb][0] * inv0), tf32q(oacc[nb][1] * inv0));
        *(float2*)(g_o + ((size_t)b * E_ + gi1) * 512 + dv) =
            make_float2(tf32q(oacc[nb][2] * inv1), tf32q(oacc[nb][3] * inv1));
    }
    // fused fixup: rescale own rows by 1/l (L2-hot) + ape column partials
    {
        int j = tid * 4;
        float4 cs = make_float4(0.f, 0.f, 0.f, 0.f);
        float* arow = abase + (size_t)i0 * E_ + j;
#pragma unroll 4
        for (int r = 0; r < 64; r++) {
            float fac = linv_s[r];
            float4 x = *(float4*)(arow + (size_t)r * E_);
            x.x *= fac; x.y *= fac; x.z *= fac; x.w *= fac;
            *(float4*)(arow + (size_t)r * E_) = x;
            cs.x += x.x; cs.y += x.y; cs.z += x.z; cs.w += x.w;
        }
        *(float4*)(g_pcs2 + ((size_t)z * 16 + iblk) * E_ + j) = cs;
    }
}

// ---------------- 6. FC + residual (cp.async double-buffered) ----------------
#define FC_SM 13824
__global__ __launch_bounds__(256) void k_fc_mma(float* __restrict__ xout) {
    extern __shared__ float fsm[];
    float* Ab[2] = { fsm, fsm + 4608 };
    float* Wb[2] = { fsm + 9216, fsm + 11520 };
    unsigned a_u[2] = { (unsigned)__cvta_generic_to_shared(Ab[0]),
                        (unsigned)__cvta_generic_to_shared(Ab[1]) };
    unsigned w_u[2] = { (unsigned)__cvta_generic_to_shared(Wb[0]),
                        (unsigned)__cvta_generic_to_shared(Wb[1]) };
    int m0 = blockIdx.x * 128, n0 = blockIdx.y * 64;
    int b = m0 >> 10, e0 = m0 & 1023;
    int tid = threadIdx.x;
    int wid = tid >> 5, lane = tid & 31;
    int g = lane >> 2, t = lane & 3;
    int warpM = wid & 3, warpN = wid >> 2;

    float acc[2][4][4] = {};

    {
#pragma unroll
        for (int i = 0; i < 4; i++) {
            int f = tid + i * 256;
            int row = f >> 3, c4 = (f & 7) * 4;
            CP_ASYNC16(a_u[0] + (unsigned)(row * 36 + c4) * 4,
                       g_o + (size_t)(m0 + row) * 512 + c4);
        }
#pragma unroll
        for (int i = 0; i < 2; i++) {
            int f = tid + i * 256;
            int row = f >> 4, c4 = (f & 15) * 4;
            CP_ASYNC16(w_u[0] + (unsigned)(row * 72 + c4) * 4,
                       g_wfcq + (size_t)row * 512 + n0 + c4);
        }
        CP_COMMIT;
    }
    int cur = 0;
    for (int k0 = 0; k0 < 512; k0 += 32) {
        CP_WAIT0;
        __syncthreads();
        if (k0 + 32 < 512) {
            unsigned au = a_u[cur ^ 1], wu = w_u[cur ^ 1];
#pragma unroll
            for (int i = 0; i < 4; i++) {
                int f = tid + i * 256;
                int row = f >> 3, c4 = (f & 7) * 4;
                CP_ASYNC16(au + (unsigned)(row * 36 + c4) * 4,
                           g_o + (size_t)(m0 + row) * 512 + k0 + 32 + c4);
            }
#pragma unroll
            for (int i = 0; i < 2; i++) {
                int f = tid + i * 256;
                int row = f >> 4, c4 = (f & 15) * 4;
                CP_ASYNC16(wu + (unsigned)(row * 72 + c4) * 4,
                           g_wfcq + (size_t)(k0 + 32 + row) * 512 + n0 + c4);
            }
            CP_COMMIT;
        }
        const unsigned* Asu = (const unsigned*)Ab[cur];
        const unsigned* Wsu = (const unsigned*)Wb[cur];
#pragma unroll
        for (int kk = 0; kk < 4; kk++) {
            int k = kk * 8;
            unsigned af[2][4], bf[4][2];
#pragma unroll
            for (int mb = 0; mb < 2; mb++) {
                int rb = warpM * 32 + mb * 16;
                af[mb][0] = Asu[(rb + g) * 36 + k + t];
                af[mb][1] = Asu[(rb + g + 8) * 36 + k + t];
                af[mb][2] = Asu[(rb + g) * 36 + k + t + 4];
                af[mb][3] = Asu[(rb + g + 8) * 36 + k + t + 4];
            }
#pragma unroll
            for (int nb = 0; nb < 4; nb++) {
                int cb = warpN * 32 + nb * 8 + g;
                bf[nb][0] = Wsu[(k + t) * 72 + cb];
                bf[nb][1] = Wsu[(k + t + 4) * 72 + cb];
            }
#pragma unroll
            for (int mb = 0; mb < 2; mb++)
#pragma unroll
                for (int nb = 0; nb < 4; nb++) MMA8(acc[mb][nb], af[mb], bf[nb])
        }
        cur ^= 1;
    }
    __syncthreads();
#pragma unroll
    for (int mb = 0; mb < 2; mb++) {
        int el0 = warpM * 32 + mb * 16 + g;
#pragma unroll
        for (int nb = 0; nb < 4; nb++) {
            int nl = warpN * 32 + nb * 8 + 2 * t;
#pragma unroll
            for (int half = 0; half < 2; half++) {
                int el = el0 + half * 8;
                const float* res = g_s + (size_t)(m0 + el) * DM_ + n0 + nl;
                fsm[(nl + 0) * 132 + el] = acc[mb][nb][half * 2 + 0] + res[0];
                fsm[(nl + 1) * 132 + el] = acc[mb][nb][half * 2 + 1] + res[1];
            }
        }
    }
    __syncthreads();
#pragma unroll
    for (int i = 0; i < 8; i++) {
        int f = tid + i * 256;
        int row = f >> 5, c4 = (f & 31) * 4;
        float4 v = *(const float4*)&fsm[row * 132 + c4];
        *(float4*)(xout + ((size_t)b * DM_ + n0 + row) * E_ + e0 + c4) = v;
    }
}

// ---------------- 7. ape final -------------------------------------------------
__global__ void k_ape_final(float* __restrict__ ape) {
    int idx = blockIdx.x * 256 + threadIdx.x;
    int b = idx >> 10, j = idx & (E_ - 1);
    float cs = 0.f;
    const float* p = g_pcs2 + (size_t)b * 8 * 16 * E_ + j;
#pragma unroll 8
    for (int k = 0; k < 128; k++) cs += p[(size_t)k * E_];
    const unsigned char* dcol = g_d8 + (size_t)b * E_ * E_ + j;
    int cnt = 0;
#pragma unroll 8
    for (int i = 0; i < E_; i++) cnt += (dcol[(size_t)i * E_] <= MAXN_) ? 1 : 0;
    ape[idx] = cs / (float)cnt;
}

// ---------------- launch ------------------------------------------------------
extern "C" void kernel_launch(void* const* d_in, const int* in_sizes, int n_in,
                              void* d_out, int out_size) {
    const float* x        = (const float*)d_in[0];
    const int*   dist     = (const int*)  d_in[1];
    const float* base_rpr = (const float*)d_in[2];
    const float* w_q      = (const float*)d_in[3];
    const float* w_k      = (const float*)d_in[4];
    const float* w_v      = (const float*)d_in[5];
    const float* w_fc     = (const float*)d_in[6];
    const float* ln_g     = (const float*)d_in[7];
    const float* ln_b     = (const float*)d_in[8];

    float* x_out = (float*)d_out;
    float* attn  = x_out + (size_t)B_ * DM_ * E_;
    float* ape   = attn  + (size_t)B_ * H_ * E_ * E_;

    static int smem_set = 0;
    if (!smem_set) {
        cudaFuncSetAttribute(k_flash, cudaFuncAttributeMaxDynamicSharedMemorySize,
                             SM_TOTAL * 4);
        cudaFuncSetAttribute(k_qkv_mma, cudaFuncAttributeMaxDynamicSharedMemorySize,
                             QKV_SM * 4);
        cudaFuncSetAttribute(k_fc_mma, cudaFuncAttributeMaxDynamicSharedMemorySize,
                             FC_SM * 4);
        smem_set = 1;
    }

    k_transpose<<<dim3(E_ / 32, DM_ / 32, B_), dim3(32, 8)>>>(x);
    k_layernorm<<<B_ * E_, 256>>>(ln_g, ln_b);
    k_pack_prep<<<3072, 256>>>(dist, w_q, w_k, w_v, w_fc);

    k_qkv_mma<<<dim3(E_ / 128, 24, B_), 256, QKV_SM * 4>>>();

    k_flash<<<dim3(16, B_ * H_), 256, SM_TOTAL * 4>>>(base_rpr, attn);
    k_fc_mma<<<dim3(B_ * E_ / 128, DM_ / 64, 1), 256, FC_SM * 4>>>(x_out);
    k_ape_final<<<(B_ * E_) / 256, 256>>>(ape);
}

// round 16
// speedup vs baseline: 1.2168x; 1.0468x over previous
#include <cuda_runtime.h>
#include <cuda_fp16.h>
#include <math.h>

#define B_  2
#define E_  1024
#define DM_ 512
#define H_  8
#define DK_ 64
#define DV_ 64
#define MAXN_ 5

__device__ __forceinline__ float tf32q(float x) {
    unsigned u;
    asm("cvt.rna.tf32.f32 %0, %1;" : "=r"(u) : "f"(x));
    return __uint_as_float(u);
}
__device__ __forceinline__ float4 tf32q4(float4 v) {
    v.x = tf32q(v.x); v.y = tf32q(v.y); v.z = tf32q(v.z); v.w = tf32q(v.w);
    return v;
}

// tf32: D(16x8) += A(16x8) * B(8x8)
#define MMA8(d, a, b)                                                        \
    asm volatile(                                                            \
        "mma.sync.aligned.m16n8k8.row.col.f32.tf32.tf32.f32 "                \
        "{%0,%1,%2,%3}, {%4,%5,%6,%7}, {%8,%9}, {%0,%1,%2,%3};\n"            \
        : "+f"((d)[0]), "+f"((d)[1]), "+f"((d)[2]), "+f"((d)[3])             \
        : "r"((a)[0]), "r"((a)[1]), "r"((a)[2]), "r"((a)[3]),                \
          "r"((b)[0]), "r"((b)[1]));

// fp16: D(16x8) += A(16x16) * B(16x8), fp32 accumulate (11-bit mantissa ops)
#define MMA16F(d, a, b)                                                      \
    asm volatile(                                                            \
        "mma.sync.aligned.m16n8k16.row.col.f32.f16.f16.f32 "                 \
        "{%0,%1,%2,%3}, {%4,%5,%6,%7}, {%8,%9}, {%0,%1,%2,%3};\n"            \
        : "+f"((d)[0]), "+f"((d)[1]), "+f"((d)[2]), "+f"((d)[3])             \
        : "r"((a)[0]), "r"((a)[1]), "r"((a)[2]), "r"((a)[3]),                \
          "r"((b)[0]), "r"((b)[1]));

#define CP_ASYNC16(su, gp)                                                   \
    asm volatile("cp.async.cg.shared.global [%0], [%1], 16;\n"               \
                 :: "r"(su), "l"(gp) : "memory")
#define CP_COMMIT  asm volatile("cp.async.commit_group;\n" ::: "memory")
#define CP_WAIT0   asm volatile("cp.async.wait_group 0;\n" ::: "memory")

// ---------------- scratch ---------------------------------------------------
__device__ float g_s  [B_*E_*DM_];          // exact (LN stats + FC residual)
__device__ float g_sq [B_*E_*DM_];          // tf32-rounded (K/V GEMM input)
__device__ float g_qn [B_*E_*DM_];          // LN output, tf32-rounded
__device__ __half g_q16[B_*H_*E_*DK_];      // fp16 (scaled 1/8)
__device__ __half g_k16[B_*H_*E_*DK_];      // fp16
__device__ __half g_v16[B_*H_*E_*DV_];      // fp16, j-pair interleaved:
                                            //  [z][jp][d*2 + (j&1)], jp=j>>1
__device__ float g_o  [B_*E_*H_*DV_];       // tf32-rounded
__device__ float g_wq  [3*DM_*(H_*DK_)];    // quantized w_q|w_k|w_v
__device__ float g_wfcq[DM_*DM_];           // quantized w_fc
__device__ float g_pcs2[B_*H_*16*E_];
__device__ unsigned char g_d8[B_*E_*E_];

// ---------------- 1. transpose x[b,d,e] -> s[b,e,d] (+tf32 copy) ------------
__global__ void k_transpose(const float* __restrict__ x) {
    __shared__ float tile[32][33];
    int b = blockIdx.z;
    int e0 = blockIdx.x * 32;
    int d0 = blockIdx.y * 32;
    int tx = threadIdx.x, ty = threadIdx.y;
#pragma unroll
    for (int r = 0; r < 4; r++) {
        int d = d0 + ty + r * 8;
        tile[ty + r * 8][tx] = x[(size_t)b * DM_ * E_ + (size_t)d * E_ + e0 + tx];
    }
    __syncthreads();
#pragma unroll
    for (int r = 0; r < 4; r++) {
        int e = e0 + ty + r * 8;
        float v = tile[tx][ty + r * 8];
        size_t idx = (size_t)b * E_ * DM_ + (size_t)e * DM_ + d0 + tx;
        g_s[idx]  = v;
        g_sq[idx] = tf32q(v);
    }
}

// ---------------- 2. LayerNorm (tf32-rounded output) -------------------------
__global__ void k_layernorm(const float* __restrict__ ln_g, const float* __restrict__ ln_b) {
    int row = blockIdx.x;
    const float* src = g_s + (size_t)row * DM_;
    int tid = threadIdx.x;
    float2 v = ((const float2*)src)[tid];
    float s1 = v.x + v.y;
    float s2 = v.x * v.x + v.y * v.y;
#pragma unroll
    for (int o = 16; o; o >>= 1) {
        s1 += __shfl_xor_sync(0xffffffff, s1, o);
        s2 += __shfl_xor_sync(0xffffffff, s2, o);
    }
    __shared__ float sh[16];
    __shared__ float s_mu, s_rstd;
    int w = tid >> 5, l = tid & 31;
    if (l == 0) { sh[w] = s1; sh[8 + w] = s2; }
    __syncthreads();
    if (tid == 0) {
        float a = 0.f, c = 0.f;
#pragma unroll
        for (int i = 0; i < 8; i++) { a += sh[i]; c += sh[8 + i]; }
        float mu  = a / (float)DM_;
        float var = c / (float)DM_ - mu * mu;
        s_mu = mu;
        s_rstd = 1.f / sqrtf(var + 1e-6f);
    }
    __syncthreads();
    float mu = s_mu, rstd = s_rstd;
    float2 gg = ((const float2*)ln_g)[tid];
    float2 bb = ((const float2*)ln_b)[tid];
    float2 o;
    o.x = tf32q((v.x - mu) * rstd * gg.x + bb.x);
    o.y = tf32q((v.y - mu) * rstd * gg.y + bb.y);
    ((float2*)(g_qn + (size_t)row * DM_))[tid] = o;
}

// ---------------- 3. pack dist -> int8 + quantize weights --------------------
__global__ void k_pack_prep(const int* __restrict__ dist,
                            const float* __restrict__ w_q,
                            const float* __restrict__ w_k,
                            const float* __restrict__ w_v,
                            const float* __restrict__ w_fc) {
    int bid = blockIdx.x;
    if (bid < 2048) {
        int idx = bid * 256 + threadIdx.x;
        int4 v = ((const int4*)dist)[idx];
        uchar4 o;
        o.x = (unsigned char)(v.x > 7 ? 7 : v.x);
        o.y = (unsigned char)(v.y > 7 ? 7 : v.y);
        o.z = (unsigned char)(v.z > 7 ? 7 : v.z);
        o.w = (unsigned char)(v.w > 7 ? 7 : v.w);
        ((uchar4*)g_d8)[idx] = o;
    } else {
        int idx = (bid - 2048) * 256 + threadIdx.x;
        int matid = idx >> 16;
        int off = idx & 65535;
        const float* src = (matid == 0) ? w_q : (matid == 1) ? w_k
                          : (matid == 2) ? w_v : w_fc;
        float4 v = tf32q4(((const float4*)src)[off]);
        float* dst = (matid < 3) ? (g_wq + (size_t)matid * DM_ * 512)
                                 : g_wfcq;
        ((float4*)dst)[off] = v;
    }
}

// ---------------- 4. fused QKV GEMM (Q/K -> fp16, V -> fp16 interleaved) -----
#define QKV_SM 13824
__global__ __launch_bounds__(256) void k_qkv_mma() {
    extern __shared__ float qsm[];
    float* Ab[2] = { qsm, qsm + 4608 };
    float* Wb[2] = { qsm + 9216, qsm + 11520 };
    unsigned a_u[2] = { (unsigned)__cvta_generic_to_shared(Ab[0]),
                        (unsigned)__cvta_generic_to_shared(Ab[1]) };
    unsigned w_u[2] = { (unsigned)__cvta_generic_to_shared(Wb[0]),
                        (unsigned)__cvta_generic_to_shared(Wb[1]) };

    int mat = blockIdx.y >> 3, h = blockIdx.y & 7, b = blockIdx.z;
    int m0 = blockIdx.x * 128;
    const float* A = (mat == 0) ? g_qn : g_sq;
    const float* W = g_wq + (size_t)mat * DM_ * 512;
    float scale = (mat == 0) ? 0.125f : 1.0f;

    int tid = threadIdx.x;
    int wid = tid >> 5, lane = tid & 31;
    int g = lane >> 2, t = lane & 3;
    int warpM = wid & 3, warpN = wid >> 2;

    float acc[2][4][4] = {};
    size_t arow_base = ((size_t)b * E_ + m0);

    {
#pragma unroll
        for (int i = 0; i < 4; i++) {
            int f = tid + i * 256;
            int row = f >> 3, c4 = (f & 7) * 4;
            CP_ASYNC16(a_u[0] + (unsigned)(row * 36 + c4) * 4,
                       A + (arow_base + row) * DM_ + c4);
        }
#pragma unroll
        for (int i = 0; i < 2; i++) {
            int f = tid + i * 256;
            int row = f >> 4, c4 = (f & 15) * 4;
            CP_ASYNC16(w_u[0] + (unsigned)(row * 72 + c4) * 4,
                       W + (size_t)row * 512 + h * 64 + c4);
        }
        CP_COMMIT;
    }
    int cur = 0;
    for (int k0 = 0; k0 < DM_; k0 += 32) {
        CP_WAIT0;
        __syncthreads();
        if (k0 + 32 < DM_) {
            unsigned au = a_u[cur ^ 1], wu = w_u[cur ^ 1];
#pragma unroll
            for (int i = 0; i < 4; i++) {
                int f = tid + i * 256;
                int row = f >> 3, c4 = (f & 7) * 4;
                CP_ASYNC16(au + (unsigned)(row * 36 + c4) * 4,
                           A + (arow_base + row) * DM_ + k0 + 32 + c4);
            }
#pragma unroll
            for (int i = 0; i < 2; i++) {
                int f = tid + i * 256;
                int row = f >> 4, c4 = (f & 15) * 4;
                CP_ASYNC16(wu + (unsigned)(row * 72 + c4) * 4,
                           W + (size_t)(k0 + 32 + row) * 512 + h * 64 + c4);
            }
            CP_COMMIT;
        }
        const unsigned* Asu = (const unsigned*)Ab[cur];
        const unsigned* Wsu = (const unsigned*)Wb[cur];
#pragma unroll
        for (int kk = 0; kk < 4; kk++) {
            int k = kk * 8;
            unsigned af[2][4], bf[4][2];
#pragma unroll
            for (int mb = 0; mb < 2; mb++) {
                int rb = warpM * 32 + mb * 16;
                af[mb][0] = Asu[(rb + g) * 36 + k + t];
                af[mb][1] = Asu[(rb + g + 8) * 36 + k + t];
                af[mb][2] = Asu[(rb + g) * 36 + k + t + 4];
                af[mb][3] = Asu[(rb + g + 8) * 36 + k + t + 4];
            }
#pragma unroll
            for (int nb = 0; nb < 4; nb++) {
                int cb = warpN * 32 + nb * 8 + g;
                bf[nb][0] = Wsu[(k + t) * 72 + cb];
                bf[nb][1] = Wsu[(k + t + 4) * 72 + cb];
            }
#pragma unroll
            for (int mb = 0; mb < 2; mb++)
#pragma unroll
                for (int nb = 0; nb < 4; nb++) MMA8(acc[mb][nb], af[mb], bf[nb])
        }
        cur ^= 1;
    }
    size_t obase = (((size_t)b * H_ + h) * E_ + m0) * 64;   // halves within z
    if (mat == 2) {
        // interleaved fp16 V: half index = (row>>1)*128 + col*2 + (row&1)
        size_t zb = (((size_t)b * H_ + h) * E_) * 64;
#pragma unroll
        for (int mb = 0; mb < 2; mb++) {
            int r0 = m0 + warpM * 32 + mb * 16 + g;
#pragma unroll
            for (int nb = 0; nb < 4; nb++) {
                int c = warpN * 32 + nb * 8 + 2 * t;
#pragma unroll
                for (int half = 0; half < 2; half++) {
                    int r = r0 + half * 8;
                    size_t base = zb + ((size_t)(r >> 1) * 128) + (r & 1);
                    g_v16[base + (c + 0) * 2] = __float2half_rn(acc[mb][nb][half * 2 + 0]);
                    g_v16[base + (c + 1) * 2] = __float2half_rn(acc[mb][nb][half * 2 + 1]);
                }
            }
        }
    } else {
        __half* o16 = (mat == 0) ? g_q16 : g_k16;
#pragma unroll
        for (int mb = 0; mb < 2; mb++) {
            int r0 = warpM * 32 + mb * 16 + g;
#pragma unroll
            for (int nb = 0; nb < 4; nb++) {
                int c = warpN * 32 + nb * 8 + 2 * t;
                __half2 h0, h1;
                h0.x = __float2half_rn(acc[mb][nb][0] * scale);
                h0.y = __float2half_rn(acc[mb][nb][1] * scale);
                h1.x = __float2half_rn(acc[mb][nb][2] * scale);
                h1.y = __float2half_rn(acc[mb][nb][3] * scale);
                *(__half2*)(o16 + obase + (size_t)r0 * 64 + c) = h0;
                *(__half2*)(o16 + obase + (size_t)(r0 + 8) * 64 + c) = h1;
            }
        }
    }
}

// ---------------- 5. flash: all-fp16 mma (QK + PV), double-buffered ----------
// grid (16, B*H): 64 i-rows/block. warps: 4(warpM,16rows) x 2(warpN,32cols).
#define SQ16   0        // Q fp16: 64x72 halves = 2304 floats
#define SK0    2304     // K fp16: 64x72 halves = 2304 floats each
#define SK1    4608
#define SV0    6912     // V fp16 interleaved: 32jp x 72 u32 = 2304 floats each
#define SV1    9216
#define SPS    11520    // P fp16: 64x72 halves = 2304 floats
#define SD0    13824    // dist: 64x80 bytes = 1280 floats each
#define SD1    15104
#define SRPR   16384
#define SQRS   16768
#define SROWL  17152
#define SLINV  17280
#define SM_TOTAL 17344  // floats -> 69376 bytes

__global__ __launch_bounds__(256, 2) void k_flash(
    const float* __restrict__ base_rpr, float* __restrict__ attn)
{
    extern __shared__ float sm[];
    __half* Qs16 = (__half*)(sm + SQ16);
    __half* Kb16[2] = { (__half*)(sm + SK0), (__half*)(sm + SK1) };
    unsigned* Vb[2] = { (unsigned*)(sm + SV0), (unsigned*)(sm + SV1) };
    __half* Ps16  = (__half*)(sm + SPS);
    unsigned char* Db[2] = { (unsigned char*)(sm + SD0), (unsigned char*)(sm + SD1) };
    float* rpr_s  = sm + SRPR;
    float* qrs    = sm + SQRS;
    float* rowl   = sm + SROWL;
    float* linv_s = sm + SLINV;
    unsigned k_u[2] = { (unsigned)__cvta_generic_to_shared(Kb16[0]),
                        (unsigned)__cvta_generic_to_shared(Kb16[1]) };
    unsigned v_u[2] = { (unsigned)__cvta_generic_to_shared(Vb[0]),
                        (unsigned)__cvta_generic_to_shared(Vb[1]) };
    unsigned d_u[2] = { (unsigned)__cvta_generic_to_shared(Db[0]),
                        (unsigned)__cvta_generic_to_shared(Db[1]) };

    int iblk = blockIdx.x, i0 = iblk * 64;
    int z = blockIdx.y, b = z >> 3;
    int tid = threadIdx.x, wid = tid >> 5, lane = tid & 31;
    int g = lane >> 2, t = lane & 3;
    int warpM = wid & 3, warpN = wid >> 2;

    const unsigned* Qsu = (const unsigned*)Qs16;   // stride 36 u32/row
    const unsigned* Psu = (const unsigned*)Ps16;   // stride 36 u32/row

    size_t qbase = ((size_t)z * E_ + i0) * 64;     // halves
    size_t kvbase = (size_t)z * E_ * 64;           // halves
    const unsigned char* dgbase = g_d8 + (size_t)b * E_ * E_;
    float* abase = attn + (size_t)z * E_ * E_;

    // prologue: Q fp16 tile, rpr
#pragma unroll
    for (int i = 0; i < 2; i++) {
        int f = tid + i * 256;
        int row = f >> 3, c = f & 7;
        *(uint4*)(Qs16 + row * 72 + c * 8) =
            *(const uint4*)(g_q16 + qbase + (size_t)row * 64 + c * 8);
    }
    for (int tt = tid; tt < 384; tt += 256) rpr_s[tt] = tf32q(base_rpr[tt]);

    // preload tile 0: K(fp16), V(fp16 interleaved), dist
    {
        const __half* kg = g_k16 + kvbase;
        const __half* vg = g_v16 + kvbase;
#pragma unroll
        for (int i = 0; i < 2; i++) {
            int f = tid + i * 256;
            int row = f >> 3, c = f & 7;
            CP_ASYNC16(k_u[0] + (unsigned)(row * 144 + c * 16),
                       kg + (size_t)row * 64 + c * 8);
        }
#pragma unroll
        for (int i = 0; i < 2; i++) {
            int f = tid + i * 256;
            int jp = f >> 4, c = f & 15;
            CP_ASYNC16(v_u[0] + (unsigned)(jp * 288 + c * 16),
                       vg + (size_t)jp * 128 + c * 8);
        }
        {
            int row = tid >> 2, c = tid & 3;
            CP_ASYNC16(d_u[0] + (unsigned)(row * 80 + c * 16),
                       dgbase + (size_t)(i0 + row) * E_ + c * 16);
        }
        CP_COMMIT;
    }
    __syncthreads();
    for (int tt = tid; tt < 384; tt += 256) {
        int row = tt / 6, c = tt % 6;
        float s = 0.f;
#pragma unroll 16
        for (int d = 0; d < 64; d++)
            s += __half2float(Qs16[row * 72 + d]) * rpr_s[c * 64 + d];
        qrs[tt] = s;
    }

    int il0 = warpM * 16 + g, il1 = il0 + 8;
    int gi0 = i0 + il0, gi1 = i0 + il1;

    float l[2] = {0.f, 0.f};
    float oacc[4][4] = {};
    int cur = 0;

    for (int jt = 0; jt < 16; jt++) {
        int j0 = jt * 64;
        CP_WAIT0;
        __syncthreads();              // buf[cur] ready; prev PV done with Ps
        if (jt < 15) {
            const __half* kg = g_k16 + kvbase + (size_t)(j0 + 64) * 64;
            const __half* vg = g_v16 + kvbase + (size_t)(j0 + 64) * 64;
            unsigned kb = k_u[cur ^ 1], vb = v_u[cur ^ 1], db = d_u[cur ^ 1];
#pragma unroll
            for (int i = 0; i < 2; i++) {
                int f = tid + i * 256;
                int row = f >> 3, c = f & 7;
                CP_ASYNC16(kb + (unsigned)(row * 144 + c * 16),
                           kg + (size_t)row * 64 + c * 8);
            }
#pragma unroll
            for (int i = 0; i < 2; i++) {
                int f = tid + i * 256;
                int jp = f >> 4, c = f & 15;
                CP_ASYNC16(vb + (unsigned)(jp * 288 + c * 16),
                           vg + (size_t)jp * 128 + c * 8);
            }
            {
                int row = tid >> 2, c = tid & 3;
                CP_ASYNC16(db + (unsigned)(row * 80 + c * 16),
                           dgbase + (size_t)(i0 + row) * E_ + j0 + 64 + c * 16);
            }
            CP_COMMIT;
        }
        const unsigned* Ksu = (const unsigned*)Kb16[cur];   // stride 36 u32/row
        const unsigned* Vsu = Vb[cur];                      // stride 72 u32/jp
        const unsigned char* Ds = Db[cur];
        // QK mma (fp16, k=16): 4 kk-chunks
        float acc[4][4] = {};
#pragma unroll
        for (int kk = 0; kk < 4; kk++) {
            int k = kk * 8;
            unsigned af[4];
            int rb = warpM * 16;
            af[0] = Qsu[(rb + g) * 36 + k + t];
            af[1] = Qsu[(rb + g + 8) * 36 + k + t];
            af[2] = Qsu[(rb + g) * 36 + k + t + 4];
            af[3] = Qsu[(rb + g + 8) * 36 + k + t + 4];
#pragma unroll
            for (int nb = 0; nb < 4; nb++) {
                unsigned bf[2];
                int cb = warpN * 32 + nb * 8 + g;
                bf[0] = Ksu[cb * 36 + k + t];
                bf[1] = Ksu[cb * 36 + k + t + 4];
                MMA16F(acc[nb], af, bf)
            }
        }
        // p = exp(x) (masked -> 0): write attn fp32 + Ps fp16 immediately
#pragma unroll
        for (int nb = 0; nb < 4; nb++) {
            int jl = warpN * 32 + nb * 8 + 2 * t;
            int j = j0 + jl;
            uchar2 d0 = *(const uchar2*)(Ds + il0 * 80 + jl);
            uchar2 d1 = *(const uchar2*)(Ds + il1 * 80 + jl);
            float p00 = (d0.x <= MAXN_) ? __expf(acc[nb][0] + qrs[il0 * 6 + d0.x]) : 0.f;
            float p01 = (d0.y <= MAXN_) ? __expf(acc[nb][1] + qrs[il0 * 6 + d0.y]) : 0.f;
            float p10 = (d1.x <= MAXN_) ? __expf(acc[nb][2] + qrs[il1 * 6 + d1.x]) : 0.f;
            float p11 = (d1.y <= MAXN_) ? __expf(acc[nb][3] + qrs[il1 * 6 + d1.y]) : 0.f;
            l[0] += p00 + p01;
            l[1] += p10 + p11;
            *(float2*)(abase + (size_t)gi0 * E_ + j) = make_float2(p00, p01);
            *(float2*)(abase + (size_t)gi1 * E_ + j) = make_float2(p10, p11);
            *(__half2*)(Ps16 + il0 * 72 + jl) = __floats2half2_rn(p00, p01);
            *(__half2*)(Ps16 + il1 * 72 + jl) = __floats2half2_rn(p10, p11);
        }
        __syncthreads();              // Ps complete
        // O += P(64x64) @ V(64x64)  (fp16, k=16): 4 kk-chunks
#pragma unroll
        for (int kk = 0; kk < 4; kk++) {
            int k = kk * 8;
            unsigned af[4];
            int rb = warpM * 16;
            af[0] = Psu[(rb + g) * 36 + k + t];
            af[1] = Psu[(rb + g + 8) * 36 + k + t];
            af[2] = Psu[(rb + g) * 36 + k + t + 4];
            af[3] = Psu[(rb + g + 8) * 36 + k + t + 4];
#pragma unroll
            for (int nb = 0; nb < 4; nb++) {
                unsigned bf[2];
                int cb = warpN * 32 + nb * 8 + g;
                bf[0] = Vsu[(k + t) * 72 + cb];
                bf[1] = Vsu[(k + t + 4) * 72 + cb];
                MMA16F(oacc[nb], af, bf)
            }
        }
        cur ^= 1;
    }
    // reduce l over t lanes + 2 warpN warps
#pragma unroll
    for (int off = 1; off < 4; off <<= 1) {
        l[0] += __shfl_xor_sync(0xffffffff, l[0], off);
        l[1] += __shfl_xor_sync(0xffffffff, l[1], off);
    }
    if (t == 0) {
        rowl[il0 * 2 + warpN] = l[0];
        rowl[il1 * 2 + warpN] = l[1];
    }
    __syncthreads();
    if (tid < 64) linv_s[tid] = 1.f / (rowl[tid * 2] + rowl[tid * 2 + 1]);
    __syncthreads();
    float inv0 = linv_s[il0], inv1 = linv_s[il1];
    int h = z & 7;
#pragma unroll
    for (int nb = 0; nb < 4; nb++) {
        int dv = h * 64 + warpN * 32 + nb * 8 + 2 * t;
        *(float2*)(g_o + ((size_t)b * E_ + gi0) * 512 + dv) =
            make_float2(tf32q(oacc[nb][0] * inv0), tf32q(oacc[nb][1] * inv0));
        *(float2*)(g_o + ((size_t)b * E_ + gi1) * 512 + dv) =
            make_float2(tf32q(oacc[nb][2] * inv1), tf32q(oacc[nb][3] * inv1));
    }
    // fused fixup: rescale own rows by 1/l (L2-hot) + ape column partials
    {
        int j = tid * 4;
        float4 cs = make_float4(0.f, 0.f, 0.f, 0.f);
        float* arow = abase + (size_t)i0 * E_ + j;
#pragma unroll 4
        for (int r = 0; r < 64; r++) {
            float fac = linv_s[r];
            float4 x = *(float4*)(arow + (size_t)r * E_);
            x.x *= fac; x.y *= fac; x.z *= fac; x.w *= fac;
            *(float4*)(arow + (size_t)r * E_) = x;
            cs.x += x.x; cs.y += x.y; cs.z += x.z; cs.w += x.w;
        }
        *(float4*)(g_pcs2 + ((size_t)z * 16 + iblk) * E_ + j) = cs;
    }
}

// ---------------- 6. FC + residual (cp.async double-buffered) ----------------
#define FC_SM 13824
__global__ __launch_bounds__(256) void k_fc_mma(float* __restrict__ xout) {
    extern __shared__ float fsm[];
    float* Ab[2] = { fsm, fsm + 4608 };
    float* Wb[2] = { fsm + 9216, fsm + 11520 };
    unsigned a_u[2] = { (unsigned)__cvta_generic_to_shared(Ab[0]),
                        (unsigned)__cvta_generic_to_shared(Ab[1]) };
    unsigned w_u[2] = { (unsigned)__cvta_generic_to_shared(Wb[0]),
                        (unsigned)__cvta_generic_to_shared(Wb[1]) };
    int m0 = blockIdx.x * 128, n0 = blockIdx.y * 64;
    int b = m0 >> 10, e0 = m0 & 1023;
    int tid = threadIdx.x;
    int wid = tid >> 5, lane = tid & 31;
    int g = lane >> 2, t = lane & 3;
    int warpM = wid & 3, warpN = wid >> 2;

    float acc[2][4][4] = {};

    {
#pragma unroll
        for (int i = 0; i < 4; i++) {
            int f = tid + i * 256;
            int row = f >> 3, c4 = (f & 7) * 4;
            CP_ASYNC16(a_u[0] + (unsigned)(row * 36 + c4) * 4,
                       g_o + (size_t)(m0 + row) * 512 + c4);
        }
#pragma unroll
        for (int i = 0; i < 2; i++) {
            int f = tid + i * 256;
            int row = f >> 4, c4 = (f & 15) * 4;
            CP_ASYNC16(w_u[0] + (unsigned)(row * 72 + c4) * 4,
                       g_wfcq + (size_t)row * 512 + n0 + c4);
        }
        CP_COMMIT;
    }
    int cur = 0;
    for (int k0 = 0; k0 < 512; k0 += 32) {
        CP_WAIT0;
        __syncthreads();
        if (k0 + 32 < 512) {
            unsigned au = a_u[cur ^ 1], wu = w_u[cur ^ 1];
#pragma unroll
            for (int i = 0; i < 4; i++) {
                int f = tid + i * 256;
                int row = f >> 3, c4 = (f & 7) * 4;
                CP_ASYNC16(au + (unsigned)(row * 36 + c4) * 4,
                           g_o + (size_t)(m0 + row) * 512 + k0 + 32 + c4);
            }
#pragma unroll
            for (int i = 0; i < 2; i++) {
                int f = tid + i * 256;
                int row = f >> 4, c4 = (f & 15) * 4;
                CP_ASYNC16(wu + (unsigned)(row * 72 + c4) * 4,
                           g_wfcq + (size_t)(k0 + 32 + row) * 512 + n0 + c4);
            }
            CP_COMMIT;
        }
        const unsigned* Asu = (const unsigned*)Ab[cur];
        const unsigned* Wsu = (const unsigned*)Wb[cur];
#pragma unroll
        for (int kk = 0; kk < 4; kk++) {
            int k = kk * 8;
            unsigned af[2][4], bf[4][2];
#pragma unroll
            for (int mb = 0; mb < 2; mb++) {
                int rb = warpM * 32 + mb * 16;
                af[mb][0] = Asu[(rb + g) * 36 + k + t];
                af[mb][1] = Asu[(rb + g + 8) * 36 + k + t];
                af[mb][2] = Asu[(rb + g) * 36 + k + t + 4];
                af[mb][3] = Asu[(rb + g + 8) * 36 + k + t + 4];
            }
#pragma unroll
            for (int nb = 0; nb < 4; nb++) {
                int cb = warpN * 32 + nb * 8 + g;
                bf[nb][0] = Wsu[(k + t) * 72 + cb];
                bf[nb][1] = Wsu[(k + t + 4) * 72 + cb];
            }
#pragma unroll
            for (int mb = 0; mb < 2; mb++)
#pragma unroll
                for (int nb = 0; nb < 4; nb++) MMA8(acc[mb][nb], af[mb], bf[nb])
        }
        cur ^= 1;
    }
    __syncthreads();
#pragma unroll
    for (int mb = 0; mb < 2; mb++) {
        int el0 = warpM * 32 + mb * 16 + g;
#pragma unroll
        for (int nb = 0; nb < 4; nb++) {
            int nl = warpN * 32 + nb * 8 + 2 * t;
#pragma unroll
            for (int half = 0; half < 2; half++) {
                int el = el0 + half * 8;
                const float* res = g_s + (size_t)(m0 + el) * DM_ + n0 + nl;
                fsm[(nl + 0) * 132 + el] = acc[mb][nb][half * 2 + 0] + res[0];
                fsm[(nl + 1) * 132 + el] = acc[mb][nb][half * 2 + 1] + res[1];
            }
        }
    }
    __syncthreads();
#pragma unroll
    for (int i = 0; i < 8; i++) {
        int f = tid + i * 256;
        int row = f >> 5, c4 = (f & 31) * 4;
        float4 v = *(const float4*)&fsm[row * 132 + c4];
        *(float4*)(xout + ((size_t)b * DM_ + n0 + row) * E_ + e0 + c4) = v;
    }
}

// ---------------- 7. ape final -------------------------------------------------
__global__ void k_ape_final(float* __restrict__ ape) {
    int idx = blockIdx.x * 256 + threadIdx.x;
    int b = idx >> 10, j = idx & (E_ - 1);
    float cs = 0.f;
    const float* p = g_pcs2 + (size_t)b * 8 * 16 * E_ + j;
#pragma unroll 8
    for (int k = 0; k < 128; k++) cs += p[(size_t)k * E_];
    const unsigned char* dcol = g_d8 + (size_t)b * E_ * E_ + j;
    int cnt = 0;
#pragma unroll 8
    for (int i = 0; i < E_; i++) cnt += (dcol[(size_t)i * E_] <= MAXN_) ? 1 : 0;
    ape[idx] = cs / (float)cnt;
}

// ---------------- launch ------------------------------------------------------
extern "C" void kernel_launch(void* const* d_in, const int* in_sizes, int n_in,
                              void* d_out, int out_size) {
    const float* x        = (const float*)d_in[0];
    const int*   dist     = (const int*)  d_in[1];
    const float* base_rpr = (const float*)d_in[2];
    const float* w_q      = (const float*)d_in[3];
    const float* w_k      = (const float*)d_in[4];
    const float* w_v      = (const float*)d_in[5];
    const float* w_fc     = (const float*)d_in[6];
    const float* ln_g     = (const float*)d_in[7];
    const float* ln_b     = (const float*)d_in[8];

    float* x_out = (float*)d_out;
    float* attn  = x_out + (size_t)B_ * DM_ * E_;
    float* ape   = attn  + (size_t)B_ * H_ * E_ * E_;

    static int smem_set = 0;
    if (!smem_set) {
        cudaFuncSetAttribute(k_flash, cudaFuncAttributeMaxDynamicSharedMemorySize,
                             SM_TOTAL * 4);
        cudaFuncSetAttribute(k_qkv_mma, cudaFuncAttributeMaxDynamicSharedMemorySize,
                             QKV_SM * 4);
        cudaFuncSetAttribute(k_fc_mma, cudaFuncAttributeMaxDynamicSharedMemorySize,
                             FC_SM * 4);
        smem_set = 1;
    }

    k_transpose<<<dim3(E_ / 32, DM_ / 32, B_), dim3(32, 8)>>>(x);
    k_layernorm<<<B_ * E_, 256>>>(ln_g, ln_b);
    k_pack_prep<<<3072, 256>>>(dist, w_q, w_k, w_v, w_fc);

    k_qkv_mma<<<dim3(E_ / 128, 24, B_), 256, QKV_SM * 4>>>();

    k_flash<<<dim3(16, B_ * H_), 256, SM_TOTAL * 4>>>(base_rpr, attn);
    k_fc_mma<<<dim3(B_ * E_ / 128, DM_ / 64, 1), 256, FC_SM * 4>>>(x_out);
    k_ape_final<<<(B_ * E_) / 256, 256>>>(ape);
}

// round 17
// speedup vs baseline: 1.2823x; 1.0538x over previous
#include <cuda_runtime.h>
#include <cuda_fp16.h>
#include <math.h>

#define B_  2
#define E_  1024
#define DM_ 512
#define H_  8
#define DK_ 64
#define DV_ 64
#define MAXN_ 5

__device__ __forceinline__ float tf32q(float x) {
    unsigned u;
    asm("cvt.rna.tf32.f32 %0, %1;" : "=r"(u) : "f"(x));
    return __uint_as_float(u);
}

// fp16: D(16x8) += A(16x16) * B(16x8), fp32 accumulate
#define MMA16F(d, a, b)                                                      \
    asm volatile(                                                            \
        "mma.sync.aligned.m16n8k16.row.col.f32.f16.f16.f32 "                 \
        "{%0,%1,%2,%3}, {%4,%5,%6,%7}, {%8,%9}, {%0,%1,%2,%3};\n"            \
        : "+f"((d)[0]), "+f"((d)[1]), "+f"((d)[2]), "+f"((d)[3])             \
        : "r"((a)[0]), "r"((a)[1]), "r"((a)[2]), "r"((a)[3]),                \
          "r"((b)[0]), "r"((b)[1]));

#define CP_ASYNC16(su, gp)                                                   \
    asm volatile("cp.async.cg.shared.global [%0], [%1], 16;\n"               \
                 :: "r"(su), "l"(gp) : "memory")
#define CP_COMMIT  asm volatile("cp.async.commit_group;\n" ::: "memory")
#define CP_WAIT0   asm volatile("cp.async.wait_group 0;\n" ::: "memory")

// ---------------- scratch ---------------------------------------------------
__device__ float  g_s  [B_*E_*DM_];          // exact (LN stats + FC residual)
__device__ __half g_s16[B_*E_*DM_];          // fp16 (K/V GEMM input)
__device__ __half g_qn16[B_*E_*DM_];         // LN output fp16
__device__ __half g_q16[B_*H_*E_*DK_];       // fp16 (scaled 1/8)
__device__ __half g_k16[B_*H_*E_*DK_];       // fp16
__device__ __half g_v16[B_*H_*E_*DV_];       // fp16, j-pair interleaved
__device__ __half g_o16[B_*E_*H_*DV_];       // fp16
__device__ __half g_w16 [3*DM_*(H_*DK_)];    // w_q|w_k|w_v u32-packed [kp][n]
__device__ __half g_wfc16[DM_*DM_];          // w_fc u32-packed [kp][n]
__device__ float g_pcs2[B_*H_*16*E_];
__device__ unsigned char g_d8[B_*E_*E_];

// ---------------- 1. transpose x[b,d,e] -> s[b,e,d] (+fp16 copy) ------------
__global__ void k_transpose(const float* __restrict__ x) {
    __shared__ float tile[32][33];
    int b = blockIdx.z;
    int e0 = blockIdx.x * 32;
    int d0 = blockIdx.y * 32;
    int tx = threadIdx.x, ty = threadIdx.y;
#pragma unroll
    for (int r = 0; r < 4; r++) {
        int d = d0 + ty + r * 8;
        tile[ty + r * 8][tx] = x[(size_t)b * DM_ * E_ + (size_t)d * E_ + e0 + tx];
    }
    __syncthreads();
#pragma unroll
    for (int r = 0; r < 4; r++) {
        int e = e0 + ty + r * 8;
        float v = tile[tx][ty + r * 8];
        size_t idx = (size_t)b * E_ * DM_ + (size_t)e * DM_ + d0 + tx;
        g_s[idx]   = v;
        g_s16[idx] = __float2half_rn(v);
    }
}

// ---------------- 2. LayerNorm (fp16 output) ---------------------------------
__global__ void k_layernorm(const float* __restrict__ ln_g, const float* __restrict__ ln_b) {
    int row = blockIdx.x;
    const float* src = g_s + (size_t)row * DM_;
    int tid = threadIdx.x;
    float2 v = ((const float2*)src)[tid];
    float s1 = v.x + v.y;
    float s2 = v.x * v.x + v.y * v.y;
#pragma unroll
    for (int o = 16; o; o >>= 1) {
        s1 += __shfl_xor_sync(0xffffffff, s1, o);
        s2 += __shfl_xor_sync(0xffffffff, s2, o);
    }
    __shared__ float sh[16];
    __shared__ float s_mu, s_rstd;
    int w = tid >> 5, l = tid & 31;
    if (l == 0) { sh[w] = s1; sh[8 + w] = s2; }
    __syncthreads();
    if (tid == 0) {
        float a = 0.f, c = 0.f;
#pragma unroll
        for (int i = 0; i < 8; i++) { a += sh[i]; c += sh[8 + i]; }
        float mu  = a / (float)DM_;
        float var = c / (float)DM_ - mu * mu;
        s_mu = mu;
        s_rstd = 1.f / sqrtf(var + 1e-6f);
    }
    __syncthreads();
    float mu = s_mu, rstd = s_rstd;
    float2 gg = ((const float2*)ln_g)[tid];
    float2 bb = ((const float2*)ln_b)[tid];
    float ox = (v.x - mu) * rstd * gg.x + bb.x;
    float oy = (v.y - mu) * rstd * gg.y + bb.y;
    ((__half2*)(g_qn16 + (size_t)row * DM_))[tid] = __floats2half2_rn(ox, oy);
}

// ---------------- 3. pack dist + k-pair-interleave weights to fp16 -----------
// grid 4096: [0,2048) dist pack; [2048,4096) weights (4 mats x 131072 u32)
__global__ void k_pack_prep(const int* __restrict__ dist,
                            const float* __restrict__ w_q,
                            const float* __restrict__ w_k,
                            const float* __restrict__ w_v,
                            const float* __restrict__ w_fc) {
    int bid = blockIdx.x;
    if (bid < 2048) {
        int idx = bid * 256 + threadIdx.x;
        int4 v = ((const int4*)dist)[idx];
        uchar4 o;
        o.x = (unsigned char)(v.x > 7 ? 7 : v.x);
        o.y = (unsigned char)(v.y > 7 ? 7 : v.y);
        o.z = (unsigned char)(v.z > 7 ? 7 : v.z);
        o.w = (unsigned char)(v.w > 7 ? 7 : v.w);
        ((uchar4*)g_d8)[idx] = o;
    } else {
        int idx = (bid - 2048) * 256 + threadIdx.x;   // 0..524287 u32 slots
        int matid = idx >> 17;                        // 131072 u32 per matrix
        int off = idx & 131071;
        int kp = off >> 9, n = off & 511;
        const float* src = (matid == 0) ? w_q : (matid == 1) ? w_k
                          : (matid == 2) ? w_v : w_fc;
        float lo = src[(size_t)(2 * kp) * 512 + n];
        float hi = src[(size_t)(2 * kp + 1) * 512 + n];
        __half* dst = (matid < 3) ? (g_w16 + (size_t)matid * 262144)
                                  : g_wfc16;
        *(__half2*)(dst + (size_t)kp * 1024 + n * 2) = __floats2half2_rn(lo, hi);
    }
}

// ---------------- 4. fused QKV GEMM (all-fp16 mma) ---------------------------
// smem floats: A 2x2560 (128 rows x 40 halves), W 2x1152 (16 kp x 72 u32)
#define QKV_SM 7424
__global__ __launch_bounds__(256) void k_qkv_mma() {
    extern __shared__ float qsm[];
    __half* Ab[2] = { (__half*)qsm, (__half*)(qsm + 2560) };
    unsigned* Wb[2] = { (unsigned*)(qsm + 5120), (unsigned*)(qsm + 6272) };
    unsigned a_u[2] = { (unsigned)__cvta_generic_to_shared(Ab[0]),
                        (unsigned)__cvta_generic_to_shared(Ab[1]) };
    unsigned w_u[2] = { (unsigned)__cvta_generic_to_shared(Wb[0]),
                        (unsigned)__cvta_generic_to_shared(Wb[1]) };

    int mat = blockIdx.y >> 3, h = blockIdx.y & 7, b = blockIdx.z;
    int m0 = blockIdx.x * 128;
    const __half* A = (mat == 0) ? g_qn16 : g_s16;
    const unsigned* W32 = (const unsigned*)g_w16 + (size_t)mat * 131072;
    float scale = (mat == 0) ? 0.125f : 1.0f;

    int tid = threadIdx.x;
    int wid = tid >> 5, lane = tid & 31;
    int g = lane >> 2, t = lane & 3;
    int warpM = wid & 3, warpN = wid >> 2;

    float acc[2][4][4] = {};
    size_t arow_base = ((size_t)b * E_ + m0);

    // preload chunk 0 (k halves 0..31, kp 0..15)
    {
#pragma unroll
        for (int i = 0; i < 2; i++) {
            int f = tid + i * 256;
            int row = f >> 2, c = f & 3;
            CP_ASYNC16(a_u[0] + (unsigned)(row * 80 + c * 16),
                       A + (arow_base + row) * DM_ + c * 8);
        }
        {
            int row = tid >> 4, c = tid & 15;
            CP_ASYNC16(w_u[0] + (unsigned)(row * 72 + c * 4) * 4,
                       W32 + (size_t)row * 512 + h * 64 + c * 4);
        }
        CP_COMMIT;
    }
    int cur = 0;
    for (int k0 = 0; k0 < DM_; k0 += 32) {
        CP_WAIT0;
        __syncthreads();
        if (k0 + 32 < DM_) {
            unsigned au = a_u[cur ^ 1], wu = w_u[cur ^ 1];
            int kp0 = (k0 + 32) >> 1;
#pragma unroll
            for (int i = 0; i < 2; i++) {
                int f = tid + i * 256;
                int row = f >> 2, c = f & 3;
                CP_ASYNC16(au + (unsigned)(row * 80 + c * 16),
                           A + (arow_base + row) * DM_ + k0 + 32 + c * 8);
            }
            {
                int row = tid >> 4, c = tid & 15;
                CP_ASYNC16(wu + (unsigned)(row * 72 + c * 4) * 4,
                           W32 + (size_t)(kp0 + row) * 512 + h * 64 + c * 4);
            }
            CP_COMMIT;
        }
        const unsigned* Asu = (const unsigned*)Ab[cur];   // stride 20 u32/row
        const unsigned* Wsu = Wb[cur];                    // stride 72 u32/kp
#pragma unroll
        for (int kk = 0; kk < 2; kk++) {
            int k = kk * 8;
            unsigned af[2][4], bf[4][2];
#pragma unroll
            for (int mb = 0; mb < 2; mb++) {
                int rb = warpM * 32 + mb * 16;
                af[mb][0] = Asu[(rb + g) * 20 + k + t];
                af[mb][1] = Asu[(rb + g + 8) * 20 + k + t];
                af[mb][2] = Asu[(rb + g) * 20 + k + t + 4];
                af[mb][3] = Asu[(rb + g + 8) * 20 + k + t + 4];
            }
#pragma unroll
            for (int nb = 0; nb < 4; nb++) {
                int cb = warpN * 32 + nb * 8 + g;
                bf[nb][0] = Wsu[(k + t) * 72 + cb];
                bf[nb][1] = Wsu[(k + t + 4) * 72 + cb];
            }
#pragma unroll
            for (int mb = 0; mb < 2; mb++)
#pragma unroll
                for (int nb = 0; nb < 4; nb++) MMA16F(acc[mb][nb], af[mb], bf[nb])
        }
        cur ^= 1;
    }
    size_t obase = (((size_t)b * H_ + h) * E_ + m0) * 64;
    if (mat == 2) {
        // interleaved fp16 V: half index = (row>>1)*128 + col*2 + (row&1)
        size_t zb = (((size_t)b * H_ + h) * E_) * 64;
#pragma unroll
        for (int mb = 0; mb < 2; mb++) {
            int r0 = m0 + warpM * 32 + mb * 16 + g;
#pragma unroll
            for (int nb = 0; nb < 4; nb++) {
                int c = warpN * 32 + nb * 8 + 2 * t;
#pragma unroll
                for (int half = 0; half < 2; half++) {
                    int r = r0 + half * 8;
                    size_t base = zb + ((size_t)(r >> 1) * 128) + (r & 1);
                    g_v16[base + (c + 0) * 2] = __float2half_rn(acc[mb][nb][half * 2 + 0]);
                    g_v16[base + (c + 1) * 2] = __float2half_rn(acc[mb][nb][half * 2 + 1]);
                }
            }
        }
    } else {
        __half* o16 = (mat == 0) ? g_q16 : g_k16;
#pragma unroll
        for (int mb = 0; mb < 2; mb++) {
            int r0 = warpM * 32 + mb * 16 + g;
#pragma unroll
            for (int nb = 0; nb < 4; nb++) {
                int c = warpN * 32 + nb * 8 + 2 * t;
                *(__half2*)(o16 + obase + (size_t)r0 * 64 + c) =
                    __floats2half2_rn(acc[mb][nb][0] * scale, acc[mb][nb][1] * scale);
                *(__half2*)(o16 + obase + (size_t)(r0 + 8) * 64 + c) =
                    __floats2half2_rn(acc[mb][nb][2] * scale, acc[mb][nb][3] * scale);
            }
        }
    }
}

// ---------------- 5. flash: all-fp16 mma (QK + PV), double-buffered ----------
#define SQ16   0
#define SK0    2304
#define SK1    4608
#define SV0    6912
#define SV1    9216
#define SPS    11520
#define SD0    13824
#define SD1    15104
#define SRPR   16384
#define SQRS   16768
#define SROWL  17152
#define SLINV  17280
#define SM_TOTAL 17344  // floats -> 69376 bytes

__global__ __launch_bounds__(256, 2) void k_flash(
    const float* __restrict__ base_rpr, float* __restrict__ attn)
{
    extern __shared__ float sm[];
    __half* Qs16 = (__half*)(sm + SQ16);
    __half* Kb16[2] = { (__half*)(sm + SK0), (__half*)(sm + SK1) };
    unsigned* Vb[2] = { (unsigned*)(sm + SV0), (unsigned*)(sm + SV1) };
    __half* Ps16  = (__half*)(sm + SPS);
    unsigned char* Db[2] = { (unsigned char*)(sm + SD0), (unsigned char*)(sm + SD1) };
    float* rpr_s  = sm + SRPR;
    float* qrs    = sm + SQRS;
    float* rowl   = sm + SROWL;
    float* linv_s = sm + SLINV;
    unsigned k_u[2] = { (unsigned)__cvta_generic_to_shared(Kb16[0]),
                        (unsigned)__cvta_generic_to_shared(Kb16[1]) };
    unsigned v_u[2] = { (unsigned)__cvta_generic_to_shared(Vb[0]),
                        (unsigned)__cvta_generic_to_shared(Vb[1]) };
    unsigned d_u[2] = { (unsigned)__cvta_generic_to_shared(Db[0]),
                        (unsigned)__cvta_generic_to_shared(Db[1]) };

    int iblk = blockIdx.x, i0 = iblk * 64;
    int z = blockIdx.y, b = z >> 3;
    int tid = threadIdx.x, wid = tid >> 5, lane = tid & 31;
    int g = lane >> 2, t = lane & 3;
    int warpM = wid & 3, warpN = wid >> 2;

    const unsigned* Qsu = (const unsigned*)Qs16;
    const unsigned* Psu = (const unsigned*)Ps16;

    size_t qbase = ((size_t)z * E_ + i0) * 64;
    size_t kvbase = (size_t)z * E_ * 64;
    const unsigned char* dgbase = g_d8 + (size_t)b * E_ * E_;
    float* abase = attn + (size_t)z * E_ * E_;

#pragma unroll
    for (int i = 0; i < 2; i++) {
        int f = tid + i * 256;
        int row = f >> 3, c = f & 7;
        *(uint4*)(Qs16 + row * 72 + c * 8) =
            *(const uint4*)(g_q16 + qbase + (size_t)row * 64 + c * 8);
    }
    for (int tt = tid; tt < 384; tt += 256) rpr_s[tt] = tf32q(base_rpr[tt]);

    {
        const __half* kg = g_k16 + kvbase;
        const __half* vg = g_v16 + kvbase;
#pragma unroll
        for (int i = 0; i < 2; i++) {
            int f = tid + i * 256;
            int row = f >> 3, c = f & 7;
            CP_ASYNC16(k_u[0] + (unsigned)(row * 144 + c * 16),
                       kg + (size_t)row * 64 + c * 8);
        }
#pragma unroll
        for (int i = 0; i < 2; i++) {
            int f = tid + i * 256;
            int jp = f >> 4, c = f & 15;
            CP_ASYNC16(v_u[0] + (unsigned)(jp * 288 + c * 16),
                       vg + (size_t)jp * 128 + c * 8);
        }
        {
            int row = tid >> 2, c = tid & 3;
            CP_ASYNC16(d_u[0] + (unsigned)(row * 80 + c * 16),
                       dgbase + (size_t)(i0 + row) * E_ + c * 16);
        }
        CP_COMMIT;
    }
    __syncthreads();
    for (int tt = tid; tt < 384; tt += 256) {
        int row = tt / 6, c = tt % 6;
        float s = 0.f;
#pragma unroll 16
        for (int d = 0; d < 64; d++)
            s += __half2float(Qs16[row * 72 + d]) * rpr_s[c * 64 + d];
        qrs[tt] = s;
    }

    int il0 = warpM * 16 + g, il1 = il0 + 8;
    int gi0 = i0 + il0, gi1 = i0 + il1;

    float l[2] = {0.f, 0.f};
    float oacc[4][4] = {};
    int cur = 0;

    for (int jt = 0; jt < 16; jt++) {
        int j0 = jt * 64;
        CP_WAIT0;
        __syncthreads();
        if (jt < 15) {
            const __half* kg = g_k16 + kvbase + (size_t)(j0 + 64) * 64;
            const __half* vg = g_v16 + kvbase + (size_t)(j0 + 64) * 64;
            unsigned kb = k_u[cur ^ 1], vb = v_u[cur ^ 1], db = d_u[cur ^ 1];
#pragma unroll
            for (int i = 0; i < 2; i++) {
                int f = tid + i * 256;
                int row = f >> 3, c = f & 7;
                CP_ASYNC16(kb + (unsigned)(row * 144 + c * 16),
                           kg + (size_t)row * 64 + c * 8);
            }
#pragma unroll
            for (int i = 0; i < 2; i++) {
                int f = tid + i * 256;
                int jp = f >> 4, c = f & 15;
                CP_ASYNC16(vb + (unsigned)(jp * 288 + c * 16),
                           vg + (size_t)jp * 128 + c * 8);
            }
            {
                int row = tid >> 2, c = tid & 3;
                CP_ASYNC16(db + (unsigned)(row * 80 + c * 16),
                           dgbase + (size_t)(i0 + row) * E_ + j0 + 64 + c * 16);
            }
            CP_COMMIT;
        }
        const unsigned* Ksu = (const unsigned*)Kb16[cur];
        const unsigned* Vsu = Vb[cur];
        const unsigned char* Ds = Db[cur];
        float acc[4][4] = {};
#pragma unroll
        for (int kk = 0; kk < 4; kk++) {
            int k = kk * 8;
            unsigned af[4];
            int rb = warpM * 16;
            af[0] = Qsu[(rb + g) * 36 + k + t];
            af[1] = Qsu[(rb + g + 8) * 36 + k + t];
            af[2] = Qsu[(rb + g) * 36 + k + t + 4];
            af[3] = Qsu[(rb + g + 8) * 36 + k + t + 4];
#pragma unroll
            for (int nb = 0; nb < 4; nb++) {
                unsigned bf[2];
                int cb = warpN * 32 + nb * 8 + g;
                bf[0] = Ksu[cb * 36 + k + t];
                bf[1] = Ksu[cb * 36 + k + t + 4];
                MMA16F(acc[nb], af, bf)
            }
        }
#pragma unroll
        for (int nb = 0; nb < 4; nb++) {
            int jl = warpN * 32 + nb * 8 + 2 * t;
            int j = j0 + jl;
            uchar2 d0 = *(const uchar2*)(Ds + il0 * 80 + jl);
            uchar2 d1 = *(const uchar2*)(Ds + il1 * 80 + jl);
            float p00 = (d0.x <= MAXN_) ? __expf(acc[nb][0] + qrs[il0 * 6 + d0.x]) : 0.f;
            float p01 = (d0.y <= MAXN_) ? __expf(acc[nb][1] + qrs[il0 * 6 + d0.y]) : 0.f;
            float p10 = (d1.x <= MAXN_) ? __expf(acc[nb][2] + qrs[il1 * 6 + d1.x]) : 0.f;
            float p11 = (d1.y <= MAXN_) ? __expf(acc[nb][3] + qrs[il1 * 6 + d1.y]) : 0.f;
            l[0] += p00 + p01;
            l[1] += p10 + p11;
            *(float2*)(abase + (size_t)gi0 * E_ + j) = make_float2(p00, p01);
            *(float2*)(abase + (size_t)gi1 * E_ + j) = make_float2(p10, p11);
            *(__half2*)(Ps16 + il0 * 72 + jl) = __floats2half2_rn(p00, p01);
            *(__half2*)(Ps16 + il1 * 72 + jl) = __floats2half2_rn(p10, p11);
        }
        __syncthreads();
#pragma unroll
        for (int kk = 0; kk < 4; kk++) {
            int k = kk * 8;
            unsigned af[4];
            int rb = warpM * 16;
            af[0] = Psu[(rb + g) * 36 + k + t];
            af[1] = Psu[(rb + g + 8) * 36 + k + t];
            af[2] = Psu[(rb + g) * 36 + k + t + 4];
            af[3] = Psu[(rb + g + 8) * 36 + k + t + 4];
#pragma unroll
            for (int nb = 0; nb < 4; nb++) {
                unsigned bf[2];
                int cb = warpN * 32 + nb * 8 + g;
                bf[0] = Vsu[(k + t) * 72 + cb];
                bf[1] = Vsu[(k + t + 4) * 72 + cb];
                MMA16F(oacc[nb], af, bf)
            }
        }
        cur ^= 1;
    }
#pragma unroll
    for (int off = 1; off < 4; off <<= 1) {
        l[0] += __shfl_xor_sync(0xffffffff, l[0], off);
        l[1] += __shfl_xor_sync(0xffffffff, l[1], off);
    }
    if (t == 0) {
        rowl[il0 * 2 + warpN] = l[0];
        rowl[il1 * 2 + warpN] = l[1];
    }
    __syncthreads();
    if (tid < 64) linv_s[tid] = 1.f / (rowl[tid * 2] + rowl[tid * 2 + 1]);
    __syncthreads();
    float inv0 = linv_s[il0], inv1 = linv_s[il1];
    int h = z & 7;
#pragma unroll
    for (int nb = 0; nb < 4; nb++) {
        int dv = h * 64 + warpN * 32 + nb * 8 + 2 * t;
        *(__half2*)(g_o16 + ((size_t)b * E_ + gi0) * 512 + dv) =
            __floats2half2_rn(oacc[nb][0] * inv0, oacc[nb][1] * inv0);
        *(__half2*)(g_o16 + ((size_t)b * E_ + gi1) * 512 + dv) =
            __floats2half2_rn(oacc[nb][2] * inv1, oacc[nb][3] * inv1);
    }
    // fused fixup: rescale own rows by 1/l (L2-hot) + ape column partials
    {
        int j = tid * 4;
        float4 cs = make_float4(0.f, 0.f, 0.f, 0.f);
        float* arow = abase + (size_t)i0 * E_ + j;
#pragma unroll 4
        for (int r = 0; r < 64; r++) {
            float fac = linv_s[r];
            float4 x = *(float4*)(arow + (size_t)r * E_);
            x.x *= fac; x.y *= fac; x.z *= fac; x.w *= fac;
            *(float4*)(arow + (size_t)r * E_) = x;
            cs.x += x.x; cs.y += x.y; cs.z += x.z; cs.w += x.w;
        }
        *(float4*)(g_pcs2 + ((size_t)z * 16 + iblk) * E_ + j) = cs;
    }
}

// ---------------- 6. FC + residual (all-fp16 mma) ----------------------------
// smem floats: A 2x2560, W 2x1152 (=7424); stage reuses fsm[0..8448)
#define FC_SM 8448
__global__ __launch_bounds__(256) void k_fc_mma(float* __restrict__ xout) {
    extern __shared__ float fsm[];
    __half* Ab[2] = { (__half*)fsm, (__half*)(fsm + 2560) };
    unsigned* Wb[2] = { (unsigned*)(fsm + 5120), (unsigned*)(fsm + 6272) };
    unsigned a_u[2] = { (unsigned)__cvta_generic_to_shared(Ab[0]),
                        (unsigned)__cvta_generic_to_shared(Ab[1]) };
    unsigned w_u[2] = { (unsigned)__cvta_generic_to_shared(Wb[0]),
                        (unsigned)__cvta_generic_to_shared(Wb[1]) };
    const unsigned* W32 = (const unsigned*)g_wfc16;
    int m0 = blockIdx.x * 128, n0 = blockIdx.y * 64;
    int b = m0 >> 10, e0 = m0 & 1023;
    int tid = threadIdx.x;
    int wid = tid >> 5, lane = tid & 31;
    int g = lane >> 2, t = lane & 3;
    int warpM = wid & 3, warpN = wid >> 2;

    float acc[2][4][4] = {};

    {
#pragma unroll
        for (int i = 0; i < 2; i++) {
            int f = tid + i * 256;
            int row = f >> 2, c = f & 3;
            CP_ASYNC16(a_u[0] + (unsigned)(row * 80 + c * 16),
                       g_o16 + (size_t)(m0 + row) * 512 + c * 8);
        }
        {
            int row = tid >> 4, c = tid & 15;
            CP_ASYNC16(w_u[0] + (unsigned)(row * 72 + c * 4) * 4,
                       W32 + (size_t)row * 512 + n0 + c * 4);
        }
        CP_COMMIT;
    }
    int cur = 0;
    for (int k0 = 0; k0 < 512; k0 += 32) {
        CP_WAIT0;
        __syncthreads();
        if (k0 + 32 < 512) {
            unsigned au = a_u[cur ^ 1], wu = w_u[cur ^ 1];
            int kp0 = (k0 + 32) >> 1;
#pragma unroll
            for (int i = 0; i < 2; i++) {
                int f = tid + i * 256;
                int row = f >> 2, c = f & 3;
                CP_ASYNC16(au + (unsigned)(row * 80 + c * 16),
                           g_o16 + (size_t)(m0 + row) * 512 + k0 + 32 + c * 8);
            }
            {
                int row = tid >> 4, c = tid & 15;
                CP_ASYNC16(wu + (unsigned)(row * 72 + c * 4) * 4,
                           W32 + (size_t)(kp0 + row) * 512 + n0 + c * 4);
            }
            CP_COMMIT;
        }
        const unsigned* Asu = (const unsigned*)Ab[cur];
        const unsigned* Wsu = Wb[cur];
#pragma unroll
        for (int kk = 0; kk < 2; kk++) {
            int k = kk * 8;
            unsigned af[2][4], bf[4][2];
#pragma unroll
            for (int mb = 0; mb < 2; mb++) {
                int rb = warpM * 32 + mb * 16;
                af[mb][0] = Asu[(rb + g) * 20 + k + t];
                af[mb][1] = Asu[(rb + g + 8) * 20 + k + t];
                af[mb][2] = Asu[(rb + g) * 20 + k + t + 4];
                af[mb][3] = Asu[(rb + g + 8) * 20 + k + t + 4];
            }
#pragma unroll
            for (int nb = 0; nb < 4; nb++) {
                int cb = warpN * 32 + nb * 8 + g;
                bf[nb][0] = Wsu[(k + t) * 72 + cb];
                bf[nb][1] = Wsu[(k + t + 4) * 72 + cb];
            }
#pragma unroll
            for (int mb = 0; mb < 2; mb++)
#pragma unroll
                for (int nb = 0; nb < 4; nb++) MMA16F(acc[mb][nb], af[mb], bf[nb])
        }
        cur ^= 1;
    }
    __syncthreads();
    // stage transposed (+ residual) in fsm, stride 132
#pragma unroll
    for (int mb = 0; mb < 2; mb++) {
        int el0 = warpM * 32 + mb * 16 + g;
#pragma unroll
        for (int nb = 0; nb < 4; nb++) {
            int nl = warpN * 32 + nb * 8 + 2 * t;
#pragma unroll
            for (int half = 0; half < 2; half++) {
                int el = el0 + half * 8;
                const float* res = g_s + (size_t)(m0 + el) * DM_ + n0 + nl;
                fsm[(nl + 0) * 132 + el] = acc[mb][nb][half * 2 + 0] + res[0];
                fsm[(nl + 1) * 132 + el] = acc[mb][nb][half * 2 + 1] + res[1];
            }
        }
    }
    __syncthreads();
#pragma unroll
    for (int i = 0; i < 8; i++) {
        int f = tid + i * 256;
        int row = f >> 5, c4 = (f & 31) * 4;
        float4 v = *(const float4*)&fsm[row * 132 + c4];
        *(float4*)(xout + ((size_t)b * DM_ + n0 + row) * E_ + e0 + c4) = v;
    }
}

// ---------------- 7. ape final -------------------------------------------------
__global__ void k_ape_final(float* __restrict__ ape) {
    int idx = blockIdx.x * 256 + threadIdx.x;
    int b = idx >> 10, j = idx & (E_ - 1);
    float cs = 0.f;
    const float* p = g_pcs2 + (size_t)b * 8 * 16 * E_ + j;
#pragma unroll 8
    for (int k = 0; k < 128; k++) cs += p[(size_t)k * E_];
    const unsigned char* dcol = g_d8 + (size_t)b * E_ * E_ + j;
    int cnt = 0;
#pragma unroll 8
    for (int i = 0; i < E_; i++) cnt += (dcol[(size_t)i * E_] <= MAXN_) ? 1 : 0;
    ape[idx] = cs / (float)cnt;
}

// ---------------- launch ------------------------------------------------------
extern "C" void kernel_launch(void* const* d_in, const int* in_sizes, int n_in,
                              void* d_out, int out_size) {
    const float* x        = (const float*)d_in[0];
    const int*   dist     = (const int*)  d_in[1];
    const float* base_rpr = (const float*)d_in[2];
    const float* w_q      = (const float*)d_in[3];
    const float* w_k      = (const float*)d_in[4];
    const float* w_v      = (const float*)d_in[5];
    const float* w_fc     = (const float*)d_in[6];
    const float* ln_g     = (const float*)d_in[7];
    const float* ln_b     = (const float*)d_in[8];

    float* x_out = (float*)d_out;
    float* attn  = x_out + (size_t)B_ * DM_ * E_;
    float* ape   = attn  + (size_t)B_ * H_ * E_ * E_;

    static int smem_set = 0;
    if (!smem_set) {
        cudaFuncSetAttribute(k_flash, cudaFuncAttributeMaxDynamicSharedMemorySize,
                             SM_TOTAL * 4);
        cudaFuncSetAttribute(k_qkv_mma, cudaFuncAttributeMaxDynamicSharedMemorySize,
                             QKV_SM * 4);
        cudaFuncSetAttribute(k_fc_mma, cudaFuncAttributeMaxDynamicSharedMemorySize,
                             FC_SM * 4);
        smem_set = 1;
    }

    k_transpose<<<dim3(E_ / 32, DM_ / 32, B_), dim3(32, 8)>>>(x);
    k_layernorm<<<B_ * E_, 256>>>(ln_g, ln_b);
    k_pack_prep<<<4096, 256>>>(dist, w_q, w_k, w_v, w_fc);

    k_qkv_mma<<<dim3(E_ / 128, 24, B_), 256, QKV_SM * 4>>>();

    k_flash<<<dim3(16, B_ * H_), 256, SM_TOTAL * 4>>>(base_rpr, attn);
    k_fc_mma<<<dim3(B_ * E_ / 128, DM_ / 64, 1), 256, FC_SM * 4>>>(x_out);
    k_ape_final<<<(B_ * E_) / 256, 256>>>(ape);
}